// round 7
// baseline (speedup 1.0000x reference)
#include <cuda_runtime.h>
#include <cuda_bf16.h>
#include <stdint.h>

#define FMAXV 3.4028235e38f

// ============================================================
// Device scratch (allocation-free). All split buffers: 2 bf16 planes
// (hi, residual) in the tensor's NATIVE layout — no transposes anywhere.
// y = att^T @ (x @ (WV@Wout)) reassociation: V/Y buffers replaced by W2/U.
// ============================================================
__device__ __nv_bfloat16 g_xS  [2ull*4096*1024];   // [n][m]
__device__ __nv_bfloat16 g_WKs [2ull*1024*1024];   // [m][d]
__device__ __nv_bfloat16 g_WQs [2ull*1024*1024];
__device__ __nv_bfloat16 g_WVs [2ull*1024*1024];
__device__ __nv_bfloat16 g_Wos [2ull*1024*1024];   // [d][m]
__device__ __nv_bfloat16 g_W2s [2ull*1024*1024];   // [m][m] = WV@Wout
__device__ __nv_bfloat16 g_KS  [2ull*4096*1024];   // [j][d]
__device__ __nv_bfloat16 g_QS  [2ull*4096*1024];   // [i][d]
__device__ __nv_bfloat16 g_US  [2ull*4096*1024];   // [j][k] = x@W2
__device__ __nv_bfloat16 g_attB[2ull*4096*4096];   // [r][a] (row-major, from softmax)
__device__ float         g_u   [1024];

// ============================================================
// Helpers (base sm_103-safe: mma.sync bf16, cp.async, ldmatrix)
// ============================================================
__device__ __forceinline__ uint32_t smem_u32(const void* p) {
    uint32_t a;
    asm("{ .reg .u64 t; cvta.to.shared.u64 t, %1; cvt.u32.u64 %0, t; }" : "=r"(a) : "l"(p));
    return a;
}
__device__ __forceinline__ void cp16(void* s, const void* g) {
    uint32_t a = smem_u32(s);
    asm volatile("cp.async.cg.shared.global [%0], [%1], 16;" :: "r"(a), "l"(g));
}
#define CP_COMMIT()  asm volatile("cp.async.commit_group;" ::: "memory")
#define CP_WAIT(N)   asm volatile("cp.async.wait_group %0;" :: "n"(N) : "memory")

__device__ __forceinline__ void ldsm4(uint32_t* r, uint32_t a) {
    asm volatile("ldmatrix.sync.aligned.m8n8.x4.shared.b16 {%0,%1,%2,%3}, [%4];"
        : "=r"(r[0]), "=r"(r[1]), "=r"(r[2]), "=r"(r[3]) : "r"(a));
}
__device__ __forceinline__ void ldsm4t(uint32_t* r, uint32_t a) {
    asm volatile("ldmatrix.sync.aligned.m8n8.x4.trans.shared.b16 {%0,%1,%2,%3}, [%4];"
        : "=r"(r[0]), "=r"(r[1]), "=r"(r[2]), "=r"(r[3]) : "r"(a));
}
__device__ __forceinline__ void mma16(float* c, const uint32_t* a, const uint32_t* b) {
    asm volatile(
        "mma.sync.aligned.m16n8k16.row.col.f32.bf16.bf16.f32 "
        "{%0,%1,%2,%3}, {%4,%5,%6,%7}, {%8,%9}, {%0,%1,%2,%3};"
        : "+f"(c[0]), "+f"(c[1]), "+f"(c[2]), "+f"(c[3])
        : "r"(a[0]), "r"(a[1]), "r"(a[2]), "r"(a[3]), "r"(b[0]), "r"(b[1]));
}
__device__ __forceinline__ uint32_t split2_u32(float v0, float v1, uint32_t* lo) {
    __nv_bfloat16 h0 = __float2bfloat16_rn(v0);
    __nv_bfloat16 h1 = __float2bfloat16_rn(v1);
    __nv_bfloat16 l0 = __float2bfloat16_rn(v0 - __bfloat162float(h0));
    __nv_bfloat16 l1 = __float2bfloat16_rn(v1 - __bfloat162float(h1));
    *lo = (uint32_t)__bfloat16_as_ushort(l0) | ((uint32_t)__bfloat16_as_ushort(l1) << 16);
    return (uint32_t)__bfloat16_as_ushort(h0) | ((uint32_t)__bfloat16_as_ushort(h1) << 16);
}

// ============================================================
// GEMM: D[m,n] = sum_k A[m,k]*B[n,k]; A,B = 2-plane bf16 split.
// TRA/TRB: global layout normal [M][K] / transposed [K][M] (ldmatrix.trans).
// 3 products/K16. Tile 128x128, BK=16, 256 thr (8 warps, 64x32),
// 4-stage cp.async, one barrier per chunk, B frags via paired ldsm4.
// EPI: 0 = bf16 split out, 1 = fp32 out, 2 = fp32 out + uAdd vector
// SKIP: 1 = fully-masked logits tile -> return, no writes
//       2 = attV: K-chunks only j < IB-129 (uniform rows via rank-1)
// ============================================================
template <int TRA, int TRB, int EPI, int SKIP>
__global__ void __launch_bounds__(256, 2)
gemm_bf16(const __nv_bfloat16* __restrict__ A, const __nv_bfloat16* __restrict__ B,
          void* __restrict__ Cv, int lda, int ldb, int ldc,
          long long planeA, long long planeB, long long planeC,
          int nch, float alpha, const float* __restrict__ uAdd)
{
    constexpr int AROW = TRA ? 136 : 24;
    constexpr int BROW = TRB ? 136 : 24;
    constexpr int APL  = TRA ? 16 * 136 : 128 * 24;
    constexpr int BPL  = TRB ? 16 * 136 : 128 * 24;
    constexpr int STG  = 2 * APL + 2 * BPL;

    const int tid = threadIdx.x;
    const int IB = blockIdx.y * 128;
    const int JB = blockIdx.x * 128;

    if (SKIP == 1 && (JB + 127 - IB) <= 256) return;

    extern __shared__ __nv_bfloat16 smh[];

    int T = nch;
    if (SKIP == 2) {
        int n1 = IB - 129; if (n1 < 0) n1 = 0;
        T = (n1 + 15) >> 4; if (T > nch) T = nch;
    }

    const int lane = tid & 31, w = tid >> 5;
    const int RW = (w >> 2) * 64, CW = (w & 3) * 32;

    // ldmatrix per-lane offsets (halves within plane)
    const int lq = lane >> 3, li = lane & 7, q2 = lq & 1, qh = lq >> 1;
    int aoff, boff;
    if (TRA) aoff = (qh * 8 + li) * AROW + RW + q2 * 8;
    else     aoff = (RW + q2 * 8 + li) * AROW + qh * 8;
    if (TRB) boff = (q2 * 8 + li) * BROW + CW + qh * 8;       // x4 pair: (nt, nt+1)
    else     boff = (CW + qh * 8 + li) * BROW + q2 * 8;
    constexpr int AMT = TRA ? 16 : 16 * AROW;                 // per-mt advance (halves)
    constexpr int BNP = TRB ? 16 : 16 * BROW;                 // per nt-PAIR advance
    const uint32_t sb0 = smem_u32(smh);

    auto issue = [&](int t) {
        int k0 = t * 16;
        __nv_bfloat16* sb = smh + (t & 3) * STG;
        #pragma unroll
        for (int it = 0; it < 2; it++) {          // A: 2 planes
            int idx = tid + it * 256;
            int pl = idx >> 8, r = idx & 255;
            __nv_bfloat16* dst; const __nv_bfloat16* src;
            if (TRA) { int row = r >> 4, ch = r & 15;
                dst = sb + pl * APL + row * AROW + ch * 8;
                src = A + (size_t)pl * planeA + (size_t)(k0 + row) * lda + IB + ch * 8;
            } else { int row = r >> 1, ch = r & 1;
                dst = sb + pl * APL + row * AROW + ch * 8;
                src = A + (size_t)pl * planeA + (size_t)(IB + row) * lda + k0 + ch * 8;
            }
            cp16(dst, src);
        }
        #pragma unroll
        for (int it = 0; it < 2; it++) {          // B: 2 planes
            int idx = tid + it * 256;
            int pl = idx >> 8, r = idx & 255;
            __nv_bfloat16* dst; const __nv_bfloat16* src;
            if (TRB) { int row = r >> 4, ch = r & 15;
                dst = sb + 2 * APL + pl * BPL + row * BROW + ch * 8;
                src = B + (size_t)pl * planeB + (size_t)(k0 + row) * ldb + JB + ch * 8;
            } else { int row = r >> 1, ch = r & 1;
                dst = sb + 2 * APL + pl * BPL + row * BROW + ch * 8;
                src = B + (size_t)pl * planeB + (size_t)(JB + row) * ldb + k0 + ch * 8;
            }
            cp16(dst, src);
        }
        CP_COMMIT();
    };

    float acc[64];
    #pragma unroll
    for (int i = 0; i < 64; i++) acc[i] = 0.f;

    if (T > 0) issue(0);
    if (T > 1) issue(1);
    if (T > 2) issue(2);

    for (int t = 0; t < T; t++) {
        if (t + 2 < T) { CP_WAIT(2); } else if (t + 1 < T) { CP_WAIT(1); } else { CP_WAIT(0); }
        __syncthreads();
        if (t + 3 < T) issue(t + 3);   // stage (t-1)&3, freed by the barrier above

        uint32_t sbb = sb0 + (uint32_t)((t & 3) * STG) * 2;
        uint32_t aH = sbb + (uint32_t)aoff * 2;
        uint32_t aM = aH + APL * 2;
        uint32_t bHa = sbb + (uint32_t)(2 * APL + boff) * 2;
        uint32_t bMa = bHa + BPL * 2;

        uint32_t af[16], am[16], bh[8], bm[8];
        #pragma unroll
        for (int mt = 0; mt < 4; mt++) {
            if (TRA) ldsm4t(af + mt * 4, aH + mt * AMT * 2);
            else     ldsm4 (af + mt * 4, aH + mt * AMT * 2);
        }
        #pragma unroll
        for (int np = 0; np < 2; np++) {          // paired B loads: (2np, 2np+1)
            if (TRB) ldsm4t(bh + np * 4, bHa + np * BNP * 2);
            else     ldsm4 (bh + np * 4, bHa + np * BNP * 2);
        }
        #pragma unroll
        for (int mt = 0; mt < 4; mt++)
            #pragma unroll
            for (int nt = 0; nt < 4; nt++)
                mma16(&acc[(mt * 4 + nt) * 4], af + mt * 4, bh + nt * 2);
        #pragma unroll
        for (int np = 0; np < 2; np++) {
            if (TRB) ldsm4t(bm + np * 4, bMa + np * BNP * 2);
            else     ldsm4 (bm + np * 4, bMa + np * BNP * 2);
        }
        #pragma unroll
        for (int mt = 0; mt < 4; mt++)
            #pragma unroll
            for (int nt = 0; nt < 4; nt++)
                mma16(&acc[(mt * 4 + nt) * 4], af + mt * 4, bm + nt * 2);
        #pragma unroll
        for (int mt = 0; mt < 4; mt++) {
            if (TRA) ldsm4t(am + mt * 4, aM + mt * AMT * 2);
            else     ldsm4 (am + mt * 4, aM + mt * AMT * 2);
        }
        #pragma unroll
        for (int mt = 0; mt < 4; mt++)
            #pragma unroll
            for (int nt = 0; nt < 4; nt++)
                mma16(&acc[(mt * 4 + nt) * 4], am + mt * 4, bh + nt * 2);
    }

    // ---------------- epilogue ----------------
    const int eg = lane >> 2, etg = lane & 3;
    #pragma unroll
    for (int mt = 0; mt < 4; mt++) {
        #pragma unroll
        for (int nt = 0; nt < 4; nt++) {
            const float* cc = &acc[(mt * 4 + nt) * 4];
            int r0 = IB + RW + mt * 16 + eg;
            int c0 = JB + CW + nt * 8 + 2 * etg;
            float ux = 0.f, uy = 0.f;
            if (EPI == 2) { float2 uu = *(const float2*)(uAdd + c0); ux = uu.x; uy = uu.y; }
            #pragma unroll
            for (int half = 0; half < 2; half++) {
                int r = r0 + half * 8;
                float v0 = cc[half * 2 + 0] * alpha + ux;
                float v1 = cc[half * 2 + 1] * alpha + uy;
                if (EPI >= 1) {
                    *(float2*)((float*)Cv + (size_t)r * ldc + c0) = make_float2(v0, v1);
                } else {
                    __nv_bfloat16* dst = (__nv_bfloat16*)Cv + (size_t)r * ldc + c0;
                    uint32_t lo;
                    uint32_t hi = split2_u32(v0, v1, &lo);
                    *(uint32_t*)dst            = hi;
                    *(uint32_t*)(dst + planeC) = lo;
                }
            }
        }
    }
}

// ============================================================
// Elementwise split to 2 bf16 planes (float4 vectorized)
// ============================================================
__global__ void __launch_bounds__(256)
split_kernel(const float* __restrict__ in, __nv_bfloat16* __restrict__ out, size_t S)
{
    size_t S4 = S >> 2;
    uint32_t* oh = (uint32_t*)out;
    uint32_t* ol = (uint32_t*)(out + S);
    for (size_t i4 = (size_t)blockIdx.x * blockDim.x + threadIdx.x; i4 < S4;
         i4 += (size_t)gridDim.x * blockDim.x) {
        float4 v = ((const float4*)in)[i4];
        uint32_t l0, l1;
        uint32_t h0 = split2_u32(v.x, v.y, &l0);
        uint32_t h1 = split2_u32(v.z, v.w, &l1);
        oh[i4 * 2] = h0; oh[i4 * 2 + 1] = h1;
        ol[i4 * 2] = l0; ol[i4 * 2 + 1] = l1;
    }
}

// ============================================================
// rank-1 uniform-row correction from U bf16 planes:
// u[k] = (1/4096) * sum_{j>=3839} (Uh+Ul)[j][k]
// ============================================================
__global__ void __launch_bounds__(128)
rank1_kernel(const __nv_bfloat16* __restrict__ Up, float* __restrict__ u)
{
    int k = blockIdx.x * 128 + threadIdx.x;   // grid 8
    const __nv_bfloat16* Uh = Up;
    const __nv_bfloat16* Ul = Up + 4096ull * 1024;
    float s = 0.f;
    #pragma unroll 4
    for (int j = 3839; j < 4096; j++) {
        size_t o = (size_t)j * 1024 + k;
        s += __bfloat162float(Uh[o]) + __bfloat162float(Ul[o]);
    }
    u[k] = s * (1.0f / 4096.0f);
}

// ============================================================
// Structured softmax + fused bf16 split, one block per row.
// Row i < 3839: live cols j >= i+257; writes fp32 att row (zero head +
// normalized live) AND bf16 hi/lo planes row-major.
// Rows i >= 3839: fp32 = 1/4096 exactly, bf16 planes = 0 (rank-1 handles them).
// ============================================================
__global__ void __launch_bounds__(256)
softmax_split(float* __restrict__ att, __nv_bfloat16* __restrict__ ab, long long PA)
{
    const int i = blockIdx.x;
    const int tid = threadIdx.x;
    float* p = att + (size_t)i * 4096;
    __nv_bfloat16* bhp = ab + (size_t)i * 4096;
    __nv_bfloat16* blp = bhp + PA;

    if (i >= 3839) {
        const float c = 1.0f / 4096.0f;
        float4 cv = make_float4(c, c, c, c);
        #pragma unroll
        for (int q = 0; q < 4; q++) ((float4*)p)[tid + q * 256] = cv;
        uint4 z = make_uint4(0, 0, 0, 0);
        #pragma unroll
        for (int q = 0; q < 2; q++) {
            ((uint4*)bhp)[tid + q * 256] = z;
            ((uint4*)blp)[tid + q * 256] = z;
        }
        return;
    }

    const int start = i + 257;
    const int s16 = start & ~15;
    const int nv4 = (4096 - s16) >> 2;
    float4* live = (float4*)(p + s16);

    float4 v[4];
    float mx = -FMAXV;
    #pragma unroll
    for (int q = 0; q < 4; q++) {
        int i4 = tid + q * 256;
        if (i4 < nv4) {
            float4 tv = live[i4];
            int j0 = s16 + i4 * 4;
            if (j0 < start) {
                if (j0 + 0 < start) tv.x = -FMAXV;
                if (j0 + 1 < start) tv.y = -FMAXV;
                if (j0 + 2 < start) tv.z = -FMAXV;
                if (j0 + 3 < start) tv.w = -FMAXV;
            }
            v[q] = tv;
            mx = fmaxf(mx, fmaxf(fmaxf(tv.x, tv.y), fmaxf(tv.z, tv.w)));
        }
    }
    #pragma unroll
    for (int o = 16; o > 0; o >>= 1) mx = fmaxf(mx, __shfl_xor_sync(0xffffffffu, mx, o));
    __shared__ float red[8];
    if ((tid & 31) == 0) red[tid >> 5] = mx;
    __syncthreads();
    mx = red[0];
    #pragma unroll
    for (int ww = 1; ww < 8; ww++) mx = fmaxf(mx, red[ww]);
    __syncthreads();

    float s = 0.f;
    #pragma unroll
    for (int q = 0; q < 4; q++) {
        if (tid + q * 256 < nv4) {
            v[q].x = expf(v[q].x - mx); s += v[q].x;
            v[q].y = expf(v[q].y - mx); s += v[q].y;
            v[q].z = expf(v[q].z - mx); s += v[q].z;
            v[q].w = expf(v[q].w - mx); s += v[q].w;
        }
    }
    #pragma unroll
    for (int o = 16; o > 0; o >>= 1) s += __shfl_xor_sync(0xffffffffu, s, o);
    if ((tid & 31) == 0) red[tid >> 5] = s;
    __syncthreads();
    s = red[0];
    #pragma unroll
    for (int ww = 1; ww < 8; ww++) s += red[ww];

    float inv = 1.0f / s;
    uint2* bhl = (uint2*)(bhp + s16);
    uint2* bll = (uint2*)(blp + s16);
    #pragma unroll
    for (int q = 0; q < 4; q++) {
        int i4 = tid + q * 256;
        if (i4 < nv4) {
            v[q].x *= inv; v[q].y *= inv; v[q].z *= inv; v[q].w *= inv;
            live[i4] = v[q];
            uint32_t l0, l1;
            uint32_t h0 = split2_u32(v[q].x, v[q].y, &l0);
            uint32_t h1 = split2_u32(v[q].z, v[q].w, &l1);
            bhl[i4] = make_uint2(h0, h1);
            bll[i4] = make_uint2(l0, l1);
        }
    }
    // zero heads
    float4 z4 = make_float4(0.f, 0.f, 0.f, 0.f);
    int nz4 = s16 >> 2;
    for (int i4 = tid; i4 < nz4; i4 += 256) ((float4*)p)[i4] = z4;
    uint2 z2 = make_uint2(0, 0);
    for (int i2 = tid; i2 < nz4; i2 += 256) {
        ((uint2*)bhp)[i2] = z2;
        ((uint2*)blp)[i2] = z2;
    }
}

// ============================================================
// Host
// ============================================================
extern "C" void kernel_launch(void* const* d_in, const int* in_sizes, int n_in,
                              void* d_out, int out_size)
{
    const float* x    = (const float*)d_in[0];
    const float* WK   = (const float*)d_in[1];
    const float* WQ   = (const float*)d_in[2];
    const float* WV   = (const float*)d_in[3];
    const float* Wout = (const float*)d_in[4];

    const int m = 1024;
    const int n = in_sizes[0] / m;   // 4096

    float* y_out = (float*)d_out;                 // [n, m]
    float* att   = y_out + (size_t)n * m;         // [n, n]

    __nv_bfloat16 *pxS, *pWK, *pWQ, *pWV, *pWo, *pW2, *pKS, *pQS, *pUS, *pattB;
    float* pu;
    cudaGetSymbolAddress((void**)&pxS,  g_xS);
    cudaGetSymbolAddress((void**)&pWK,  g_WKs);
    cudaGetSymbolAddress((void**)&pWQ,  g_WQs);
    cudaGetSymbolAddress((void**)&pWV,  g_WVs);
    cudaGetSymbolAddress((void**)&pWo,  g_Wos);
    cudaGetSymbolAddress((void**)&pW2,  g_W2s);
    cudaGetSymbolAddress((void**)&pKS,  g_KS);
    cudaGetSymbolAddress((void**)&pQS,  g_QS);
    cudaGetSymbolAddress((void**)&pUS,  g_US);
    cudaGetSymbolAddress((void**)&pattB, g_attB);
    cudaGetSymbolAddress((void**)&pu,   g_u);

    // dynamic smem per instantiation (4 stages)
    const int SM01 = 4 * (2 * (128 * 24) + 2 * (16 * 136)) * 2;  // 83968
    const int SM00 = 4 * (4 * (128 * 24)) * 2;                   // 98304
    const int SM11 = 4 * (4 * (16 * 136)) * 2;                   // 69632

    cudaFuncSetAttribute(gemm_bf16<0, 1, 0, 0>, cudaFuncAttributeMaxDynamicSharedMemorySize, SM01);
    cudaFuncSetAttribute(gemm_bf16<0, 0, 1, 1>, cudaFuncAttributeMaxDynamicSharedMemorySize, SM00);
    cudaFuncSetAttribute(gemm_bf16<1, 1, 2, 2>, cudaFuncAttributeMaxDynamicSharedMemorySize, SM11);

    const long long PX = 4096LL * 1024;
    const long long PW = 1024LL * 1024;
    const long long PA = 4096LL * 4096;

    // Elementwise splits only — NO transposes.
    split_kernel<<<2048, 256>>>(x,    pxS, (size_t)n * m);
    split_kernel<<<512,  256>>>(WK,   pWK, (size_t)m * m);
    split_kernel<<<512,  256>>>(WQ,   pWQ, (size_t)m * m);
    split_kernel<<<512,  256>>>(WV,   pWV, (size_t)m * m);
    split_kernel<<<512,  256>>>(Wout, pWo, (size_t)m * m);

    dim3 g1(8, 32);
    // K = x@WK, Q = 0.06*(x@WQ)  (A normal, B=[K][N] trans) -> bf16 split
    gemm_bf16<0, 1, 0, 0><<<g1, 256, SM01>>>(pxS, pWK, pKS, 1024, 1024, 1024, PX, PW, PX, 64, 1.0f, nullptr);
    gemm_bf16<0, 1, 0, 0><<<g1, 256, SM01>>>(pxS, pWQ, pQS, 1024, 1024, 1024, PX, PW, PX, 64, 0.06f, nullptr);

    // W2 = WV@Wout  (A=WV [M][K] normal, B=Wout [K][N] trans) -> bf16 split
    gemm_bf16<0, 1, 0, 0><<<dim3(8, 8), 256, SM01>>>(pWV, pWo, pW2, 1024, 1024, 1024, PW, PW, PW, 64, 1.0f, nullptr);
    // U = x@W2 -> bf16 split
    gemm_bf16<0, 1, 0, 0><<<g1, 256, SM01>>>(pxS, pW2, pUS, 1024, 1024, 1024, PX, PW, PX, 64, 1.0f, nullptr);

    // logits = Q@K^T (A normal, B normal) -> fp32 att in d_out
    gemm_bf16<0, 0, 1, 1><<<dim3(32, 32), 256, SM00>>>(pQS, pKS, att, 1024, 1024, 4096, PX, PX, 0, 64, 1.0f, nullptr);

    // softmax + fused bf16 split (row-major planes)
    softmax_split<<<n, 256>>>(att, pattB, PA);

    // rank-1 uniform-row vector from U planes
    rank1_kernel<<<8, 128>>>(pUS, pu);

    // y = att^T @ U + u  (A=att [K][M] trans, B=U [K][N] trans) -> fp32 y_out
    gemm_bf16<1, 1, 2, 2><<<g1, 256, SM11>>>(pattB, pUS, y_out, 4096, 1024, 1024, PA, PX, 0, 256, 1.0f, pu);
}

// round 9
// speedup vs baseline: 1.1939x; 1.1939x over previous
#include <cuda_runtime.h>
#include <cuda_bf16.h>
#include <stdint.h>

#define FMAXV 3.4028235e38f

// ============================================================
// Device scratch (allocation-free). All split buffers: 2 bf16 planes
// (hi, residual) in the tensor's NATIVE layout — no transposes anywhere.
// Reassociation: y = att^T @ (x @ (WV@Wout)) + u  (Yout GEMM deleted).
// ============================================================
__device__ __nv_bfloat16 g_xS  [2ull*4096*1024];   // [n][m]
__device__ __nv_bfloat16 g_WKs [2ull*1024*1024];   // [m][d]
__device__ __nv_bfloat16 g_WQs [2ull*1024*1024];
__device__ __nv_bfloat16 g_WVs [2ull*1024*1024];
__device__ __nv_bfloat16 g_Wos [2ull*1024*1024];   // [d][m]
__device__ __nv_bfloat16 g_W2s [2ull*1024*1024];   // [m][m] = WV@Wout
__device__ __nv_bfloat16 g_KS  [2ull*4096*1024];   // [j][d]
__device__ __nv_bfloat16 g_QS  [2ull*4096*1024];   // [i][d]
__device__ __nv_bfloat16 g_US  [2ull*4096*1024];   // [j][k] = x@W2
__device__ __nv_bfloat16 g_attB[2ull*4096*4096];   // [r][a] (row-major, from softmax)
__device__ float         g_u   [1024];

// ============================================================
// Helpers (base sm_103-safe: mma.sync bf16, cp.async, ldmatrix)
// ============================================================
__device__ __forceinline__ uint32_t smem_u32(const void* p) {
    uint32_t a;
    asm("{ .reg .u64 t; cvta.to.shared.u64 t, %1; cvt.u32.u64 %0, t; }" : "=r"(a) : "l"(p));
    return a;
}
__device__ __forceinline__ void cp16(void* s, const void* g) {
    uint32_t a = smem_u32(s);
    asm volatile("cp.async.cg.shared.global [%0], [%1], 16;" :: "r"(a), "l"(g));
}
#define CP_COMMIT()  asm volatile("cp.async.commit_group;" ::: "memory")
#define CP_WAIT(N)   asm volatile("cp.async.wait_group %0;" :: "n"(N) : "memory")

__device__ __forceinline__ void ldsm4(uint32_t* r, uint32_t a) {
    asm volatile("ldmatrix.sync.aligned.m8n8.x4.shared.b16 {%0,%1,%2,%3}, [%4];"
        : "=r"(r[0]), "=r"(r[1]), "=r"(r[2]), "=r"(r[3]) : "r"(a));
}
__device__ __forceinline__ void ldsm4t(uint32_t* r, uint32_t a) {
    asm volatile("ldmatrix.sync.aligned.m8n8.x4.trans.shared.b16 {%0,%1,%2,%3}, [%4];"
        : "=r"(r[0]), "=r"(r[1]), "=r"(r[2]), "=r"(r[3]) : "r"(a));
}
__device__ __forceinline__ void ldsm2(uint32_t* r, uint32_t a) {
    asm volatile("ldmatrix.sync.aligned.m8n8.x2.shared.b16 {%0,%1}, [%2];"
        : "=r"(r[0]), "=r"(r[1]) : "r"(a));
}
__device__ __forceinline__ void ldsm2t(uint32_t* r, uint32_t a) {
    asm volatile("ldmatrix.sync.aligned.m8n8.x2.trans.shared.b16 {%0,%1}, [%2];"
        : "=r"(r[0]), "=r"(r[1]) : "r"(a));
}
__device__ __forceinline__ void mma16(float* c, const uint32_t* a, const uint32_t* b) {
    asm volatile(
        "mma.sync.aligned.m16n8k16.row.col.f32.bf16.bf16.f32 "
        "{%0,%1,%2,%3}, {%4,%5,%6,%7}, {%8,%9}, {%0,%1,%2,%3};"
        : "+f"(c[0]), "+f"(c[1]), "+f"(c[2]), "+f"(c[3])
        : "r"(a[0]), "r"(a[1]), "r"(a[2]), "r"(a[3]), "r"(b[0]), "r"(b[1]));
}
__device__ __forceinline__ uint32_t split2_u32(float v0, float v1, uint32_t* lo) {
    __nv_bfloat16 h0 = __float2bfloat16_rn(v0);
    __nv_bfloat16 h1 = __float2bfloat16_rn(v1);
    __nv_bfloat16 l0 = __float2bfloat16_rn(v0 - __bfloat162float(h0));
    __nv_bfloat16 l1 = __float2bfloat16_rn(v1 - __bfloat162float(h1));
    *lo = (uint32_t)__bfloat16_as_ushort(l0) | ((uint32_t)__bfloat16_as_ushort(l1) << 16);
    return (uint32_t)__bfloat16_as_ushort(h0) | ((uint32_t)__bfloat16_as_ushort(h1) << 16);
}

// ============================================================
// GEMM (R6 core, unchanged schedule): D[m,n] = sum_k A[m,k]*B[n,k].
// A,B = 2-plane bf16 split; 3 products/K16 (Ah*Bh + Ah*Bm + Am*Bh).
// Tile 128x128, BK=16, 256 thr (8 warps, 64x32), 4-stage cp.async,
// one barrier per chunk, issue() at END of loop body (LDSMs first).
// EPI: 0 = bf16 split out, 1 = fp32 out, 2 = fp32 out + uAdd vector
// SKIP: 1 = fully-masked logits tile -> return, no writes
//       2 = attV: K-chunks only j < IB-129 (uniform rows via rank-1)
// ============================================================
template <int TRA, int TRB, int EPI, int SKIP>
__global__ void __launch_bounds__(256, 2)
gemm_bf16(const __nv_bfloat16* __restrict__ A, const __nv_bfloat16* __restrict__ B,
          void* __restrict__ Cv, int lda, int ldb, int ldc,
          long long planeA, long long planeB, long long planeC,
          int nch, float alpha, const float* __restrict__ uAdd)
{
    constexpr int AROW = TRA ? 136 : 24;          // padded row strides (halves)
    constexpr int BROW = TRB ? 136 : 24;
    constexpr int APL  = TRA ? 16 * 136 : 128 * 24;
    constexpr int BPL  = TRB ? 16 * 136 : 128 * 24;
    constexpr int STG  = 2 * APL + 2 * BPL;       // Ah, Am, Bh, Bm (halves)

    const int tid = threadIdx.x;
    const int IB = blockIdx.y * 128;
    const int JB = blockIdx.x * 128;

    if (SKIP == 1 && (JB + 127 - IB) <= 256) return;

    extern __shared__ __nv_bfloat16 smh[];

    int T = nch;
    if (SKIP == 2) {
        int n1 = IB - 129; if (n1 < 0) n1 = 0;
        T = (n1 + 15) >> 4; if (T > nch) T = nch;
    }

    const int lane = tid & 31, w = tid >> 5;
    const int RW = (w >> 2) * 64, CW = (w & 3) * 32;

    // ldmatrix per-lane offsets (halves within plane)
    const int lq = lane >> 3, li = lane & 7, q2 = lq & 1;
    int aoff, boff;
    if (TRA) aoff = ((lq >> 1) * 8 + li) * AROW + RW + (lq & 1) * 8;
    else     aoff = (RW + (lq & 1) * 8 + li) * AROW + (lq >> 1) * 8;
    if (TRB) boff = (q2 * 8 + li) * BROW + CW;
    else     boff = (CW + li) * BROW + q2 * 8;
    constexpr int AMT = TRA ? 16 : 16 * AROW;     // per-mt advance
    constexpr int BNT = TRB ? 8 : 8 * BROW;       // per-nt advance
    const uint32_t sb0 = smem_u32(smh);

    auto issue = [&](int t) {
        int k0 = t * 16;
        __nv_bfloat16* sb = smh + (t & 3) * STG;
        #pragma unroll
        for (int it = 0; it < 2; it++) {          // A: 2 planes
            int idx = tid + it * 256;
            int pl = idx >> 8, r = idx & 255;
            __nv_bfloat16* dst; const __nv_bfloat16* src;
            if (TRA) { int row = r >> 4, ch = r & 15;
                dst = sb + pl * APL + row * AROW + ch * 8;
                src = A + (size_t)pl * planeA + (size_t)(k0 + row) * lda + IB + ch * 8;
            } else { int row = r >> 1, ch = r & 1;
                dst = sb + pl * APL + row * AROW + ch * 8;
                src = A + (size_t)pl * planeA + (size_t)(IB + row) * lda + k0 + ch * 8;
            }
            cp16(dst, src);
        }
        #pragma unroll
        for (int it = 0; it < 2; it++) {          // B: 2 planes
            int idx = tid + it * 256;
            int pl = idx >> 8, r = idx & 255;
            __nv_bfloat16* dst; const __nv_bfloat16* src;
            if (TRB) { int row = r >> 4, ch = r & 15;
                dst = sb + 2 * APL + pl * BPL + row * BROW + ch * 8;
                src = B + (size_t)pl * planeB + (size_t)(k0 + row) * ldb + JB + ch * 8;
            } else { int row = r >> 1, ch = r & 1;
                dst = sb + 2 * APL + pl * BPL + row * BROW + ch * 8;
                src = B + (size_t)pl * planeB + (size_t)(JB + row) * ldb + k0 + ch * 8;
            }
            cp16(dst, src);
        }
        CP_COMMIT();
    };

    float acc[64];
    #pragma unroll
    for (int i = 0; i < 64; i++) acc[i] = 0.f;

    if (T > 0) issue(0);
    if (T > 1) issue(1);
    if (T > 2) issue(2);

    for (int t = 0; t < T; t++) {
        if (t + 2 < T) { CP_WAIT(2); } else if (t + 1 < T) { CP_WAIT(1); } else { CP_WAIT(0); }
        __syncthreads();

        uint32_t sbb = sb0 + (uint32_t)((t & 3) * STG) * 2;
        uint32_t aH = sbb + (uint32_t)aoff * 2;
        uint32_t aM = aH + APL * 2;
        uint32_t bHa = sbb + (uint32_t)(2 * APL + boff) * 2;
        uint32_t bMa = bHa + BPL * 2;

        uint32_t af[16], am[16], bh[8], bm[8];
        #pragma unroll
        for (int mt = 0; mt < 4; mt++) {
            if (TRA) ldsm4t(af + mt * 4, aH + mt * AMT * 2);
            else     ldsm4 (af + mt * 4, aH + mt * AMT * 2);
        }
        #pragma unroll
        for (int nt = 0; nt < 4; nt++) {
            if (TRB) ldsm2t(bh + nt * 2, bHa + nt * BNT * 2);
            else     ldsm2 (bh + nt * 2, bHa + nt * BNT * 2);
        }
        #pragma unroll
        for (int mt = 0; mt < 4; mt++)
            #pragma unroll
            for (int nt = 0; nt < 4; nt++)
                mma16(&acc[(mt * 4 + nt) * 4], af + mt * 4, bh + nt * 2);
        #pragma unroll
        for (int nt = 0; nt < 4; nt++) {
            if (TRB) ldsm2t(bm + nt * 2, bMa + nt * BNT * 2);
            else     ldsm2 (bm + nt * 2, bMa + nt * BNT * 2);
        }
        #pragma unroll
        for (int mt = 0; mt < 4; mt++)
            #pragma unroll
            for (int nt = 0; nt < 4; nt++)
                mma16(&acc[(mt * 4 + nt) * 4], af + mt * 4, bm + nt * 2);
        #pragma unroll
        for (int mt = 0; mt < 4; mt++) {
            if (TRA) ldsm4t(am + mt * 4, aM + mt * AMT * 2);
            else     ldsm4 (am + mt * 4, aM + mt * AMT * 2);
        }
        #pragma unroll
        for (int mt = 0; mt < 4; mt++)
            #pragma unroll
            for (int nt = 0; nt < 4; nt++)
                mma16(&acc[(mt * 4 + nt) * 4], am + mt * 4, bh + nt * 2);

        if (t + 3 < T) issue(t + 3);   // writes stage (t-1)&3, freed by top barrier
    }

    // ---------------- epilogue ----------------
    const int eg = lane >> 2, etg = lane & 3;
    #pragma unroll
    for (int mt = 0; mt < 4; mt++) {
        #pragma unroll
        for (int nt = 0; nt < 4; nt++) {
            const float* cc = &acc[(mt * 4 + nt) * 4];
            int r0 = IB + RW + mt * 16 + eg;
            int c0 = JB + CW + nt * 8 + 2 * etg;
            float ux = 0.f, uy = 0.f;
            if (EPI == 2) { float2 uu = *(const float2*)(uAdd + c0); ux = uu.x; uy = uu.y; }
            #pragma unroll
            for (int half = 0; half < 2; half++) {
                int r = r0 + half * 8;
                float v0 = cc[half * 2 + 0] * alpha + ux;
                float v1 = cc[half * 2 + 1] * alpha + uy;
                if (EPI >= 1) {
                    *(float2*)((float*)Cv + (size_t)r * ldc + c0) = make_float2(v0, v1);
                } else {
                    __nv_bfloat16* dst = (__nv_bfloat16*)Cv + (size_t)r * ldc + c0;
                    uint32_t lo;
                    uint32_t hi = split2_u32(v0, v1, &lo);
                    *(uint32_t*)dst            = hi;
                    *(uint32_t*)(dst + planeC) = lo;
                }
            }
        }
    }
}

// ============================================================
// Elementwise split to 2 bf16 planes (float4 vectorized)
// ============================================================
__global__ void __launch_bounds__(256)
split_kernel(const float* __restrict__ in, __nv_bfloat16* __restrict__ out, size_t S)
{
    size_t S4 = S >> 2;
    uint32_t* oh = (uint32_t*)out;
    uint32_t* ol = (uint32_t*)(out + S);
    for (size_t i4 = (size_t)blockIdx.x * blockDim.x + threadIdx.x; i4 < S4;
         i4 += (size_t)gridDim.x * blockDim.x) {
        float4 v = ((const float4*)in)[i4];
        uint32_t l0, l1;
        uint32_t h0 = split2_u32(v.x, v.y, &l0);
        uint32_t h1 = split2_u32(v.z, v.w, &l1);
        oh[i4 * 2] = h0; oh[i4 * 2 + 1] = h1;
        ol[i4 * 2] = l0; ol[i4 * 2 + 1] = l1;
    }
}

// ============================================================
// rank-1 uniform-row correction from U bf16 planes (parallel over j):
// u[k] = (1/4096) * sum_{j>=3839} (Uh+Ul)[j][k]
// grid 8 x 1024 threads: 8 j-slices per block, shared reduce.
// ============================================================
__global__ void __launch_bounds__(1024)
rank1_kernel(const __nv_bfloat16* __restrict__ Up, float* __restrict__ u)
{
    __shared__ float part[8][128];
    const int kl = threadIdx.x & 127;
    const int js = threadIdx.x >> 7;          // 0..7
    const int k = blockIdx.x * 128 + kl;
    const __nv_bfloat16* Uh = Up;
    const __nv_bfloat16* Ul = Up + 4096ull * 1024;
    float s = 0.f;
    for (int j = 3839 + js; j < 4096; j += 8) {
        size_t o = (size_t)j * 1024 + k;
        s += __bfloat162float(Uh[o]) + __bfloat162float(Ul[o]);
    }
    part[js][kl] = s;
    __syncthreads();
    if (threadIdx.x < 128) {
        float t = 0.f;
        #pragma unroll
        for (int q = 0; q < 8; q++) t += part[q][threadIdx.x];
        u[k] = t * (1.0f / 4096.0f);
    }
}

// ============================================================
// Structured softmax + fused bf16 split, one block per row.
// Row i < 3839: live cols j >= i+257; writes fp32 att row (zero head +
// normalized live) AND bf16 hi/lo planes row-major.
// Rows i >= 3839: fp32 = 1/4096 exactly, bf16 planes = 0 (rank-1 handles them).
// ============================================================
__global__ void __launch_bounds__(256)
softmax_split(float* __restrict__ att, __nv_bfloat16* __restrict__ ab, long long PA)
{
    const int i = blockIdx.x;
    const int tid = threadIdx.x;
    float* p = att + (size_t)i * 4096;
    __nv_bfloat16* bhp = ab + (size_t)i * 4096;
    __nv_bfloat16* blp = bhp + PA;

    if (i >= 3839) {
        const float c = 1.0f / 4096.0f;
        float4 cv = make_float4(c, c, c, c);
        #pragma unroll
        for (int q = 0; q < 4; q++) ((float4*)p)[tid + q * 256] = cv;
        uint4 z = make_uint4(0, 0, 0, 0);
        #pragma unroll
        for (int q = 0; q < 2; q++) {
            ((uint4*)bhp)[tid + q * 256] = z;
            ((uint4*)blp)[tid + q * 256] = z;
        }
        return;
    }

    const int start = i + 257;
    const int s16 = start & ~15;
    const int nv4 = (4096 - s16) >> 2;
    float4* live = (float4*)(p + s16);

    float4 v[4];
    float mx = -FMAXV;
    #pragma unroll
    for (int q = 0; q < 4; q++) {
        int i4 = tid + q * 256;
        if (i4 < nv4) {
            float4 tv = live[i4];
            int j0 = s16 + i4 * 4;
            if (j0 < start) {
                if (j0 + 0 < start) tv.x = -FMAXV;
                if (j0 + 1 < start) tv.y = -FMAXV;
                if (j0 + 2 < start) tv.z = -FMAXV;
                if (j0 + 3 < start) tv.w = -FMAXV;
            }
            v[q] = tv;
            mx = fmaxf(mx, fmaxf(fmaxf(tv.x, tv.y), fmaxf(tv.z, tv.w)));
        }
    }
    #pragma unroll
    for (int o = 16; o > 0; o >>= 1) mx = fmaxf(mx, __shfl_xor_sync(0xffffffffu, mx, o));
    __shared__ float red[8];
    if ((tid & 31) == 0) red[tid >> 5] = mx;
    __syncthreads();
    mx = red[0];
    #pragma unroll
    for (int ww = 1; ww < 8; ww++) mx = fmaxf(mx, red[ww]);
    __syncthreads();

    float s = 0.f;
    #pragma unroll
    for (int q = 0; q < 4; q++) {
        if (tid + q * 256 < nv4) {
            v[q].x = expf(v[q].x - mx); s += v[q].x;
            v[q].y = expf(v[q].y - mx); s += v[q].y;
            v[q].z = expf(v[q].z - mx); s += v[q].z;
            v[q].w = expf(v[q].w - mx); s += v[q].w;
        }
    }
    #pragma unroll
    for (int o = 16; o > 0; o >>= 1) s += __shfl_xor_sync(0xffffffffu, s, o);
    if ((tid & 31) == 0) red[tid >> 5] = s;
    __syncthreads();
    s = red[0];
    #pragma unroll
    for (int ww = 1; ww < 8; ww++) s += red[ww];

    float inv = 1.0f / s;
    uint2* bhl = (uint2*)(bhp + s16);
    uint2* bll = (uint2*)(blp + s16);
    #pragma unroll
    for (int q = 0; q < 4; q++) {
        int i4 = tid + q * 256;
        if (i4 < nv4) {
            v[q].x *= inv; v[q].y *= inv; v[q].z *= inv; v[q].w *= inv;
            live[i4] = v[q];
            uint32_t l0, l1;
            uint32_t h0 = split2_u32(v[q].x, v[q].y, &l0);
            uint32_t h1 = split2_u32(v[q].z, v[q].w, &l1);
            bhl[i4] = make_uint2(h0, h1);
            bll[i4] = make_uint2(l0, l1);
        }
    }
    // zero heads
    float4 z4 = make_float4(0.f, 0.f, 0.f, 0.f);
    int nz4 = s16 >> 2;
    for (int i4 = tid; i4 < nz4; i4 += 256) ((float4*)p)[i4] = z4;
    uint2 z2 = make_uint2(0, 0);
    for (int i2 = tid; i2 < nz4; i2 += 256) {
        ((uint2*)bhp)[i2] = z2;
        ((uint2*)blp)[i2] = z2;
    }
}

// ============================================================
// Host
// ============================================================
extern "C" void kernel_launch(void* const* d_in, const int* in_sizes, int n_in,
                              void* d_out, int out_size)
{
    const float* x    = (const float*)d_in[0];
    const float* WK   = (const float*)d_in[1];
    const float* WQ   = (const float*)d_in[2];
    const float* WV   = (const float*)d_in[3];
    const float* Wout = (const float*)d_in[4];

    const int m = 1024;
    const int n = in_sizes[0] / m;   // 4096

    float* y_out = (float*)d_out;                 // [n, m]
    float* att   = y_out + (size_t)n * m;         // [n, n]

    __nv_bfloat16 *pxS, *pWK, *pWQ, *pWV, *pWo, *pW2, *pKS, *pQS, *pUS, *pattB;
    float* pu;
    cudaGetSymbolAddress((void**)&pxS,  g_xS);
    cudaGetSymbolAddress((void**)&pWK,  g_WKs);
    cudaGetSymbolAddress((void**)&pWQ,  g_WQs);
    cudaGetSymbolAddress((void**)&pWV,  g_WVs);
    cudaGetSymbolAddress((void**)&pWo,  g_Wos);
    cudaGetSymbolAddress((void**)&pW2,  g_W2s);
    cudaGetSymbolAddress((void**)&pKS,  g_KS);
    cudaGetSymbolAddress((void**)&pQS,  g_QS);
    cudaGetSymbolAddress((void**)&pUS,  g_US);
    cudaGetSymbolAddress((void**)&pattB, g_attB);
    cudaGetSymbolAddress((void**)&pu,   g_u);

    // dynamic smem per instantiation (4 stages)
    const int SM01 = 4 * (2 * (128 * 24) + 2 * (16 * 136)) * 2;  // 83968
    const int SM00 = 4 * (4 * (128 * 24)) * 2;                   // 98304
    const int SM11 = 4 * (4 * (16 * 136)) * 2;                   // 69632

    cudaFuncSetAttribute(gemm_bf16<0, 1, 0, 0>, cudaFuncAttributeMaxDynamicSharedMemorySize, SM01);
    cudaFuncSetAttribute(gemm_bf16<0, 0, 1, 1>, cudaFuncAttributeMaxDynamicSharedMemorySize, SM00);
    cudaFuncSetAttribute(gemm_bf16<1, 1, 2, 2>, cudaFuncAttributeMaxDynamicSharedMemorySize, SM11);

    const long long PX = 4096LL * 1024;
    const long long PW = 1024LL * 1024;
    const long long PA = 4096LL * 4096;

    // Elementwise splits only — NO transposes.
    split_kernel<<<2048, 256>>>(x,    pxS, (size_t)n * m);
    split_kernel<<<512,  256>>>(WK,   pWK, (size_t)m * m);
    split_kernel<<<512,  256>>>(WQ,   pWQ, (size_t)m * m);
    split_kernel<<<512,  256>>>(WV,   pWV, (size_t)m * m);
    split_kernel<<<512,  256>>>(Wout, pWo, (size_t)m * m);

    dim3 g1(8, 32);
    // K = x@WK, Q = 0.06*(x@WQ)  (A normal, B=[K][N] trans) -> bf16 split
    gemm_bf16<0, 1, 0, 0><<<g1, 256, SM01>>>(pxS, pWK, pKS, 1024, 1024, 1024, PX, PW, PX, 64, 1.0f, nullptr);
    gemm_bf16<0, 1, 0, 0><<<g1, 256, SM01>>>(pxS, pWQ, pQS, 1024, 1024, 1024, PX, PW, PX, 64, 0.06f, nullptr);

    // W2 = WV@Wout -> bf16 split; U = x@W2 -> bf16 split
    gemm_bf16<0, 1, 0, 0><<<dim3(8, 8), 256, SM01>>>(pWV, pWo, pW2, 1024, 1024, 1024, PW, PW, PW, 64, 1.0f, nullptr);
    gemm_bf16<0, 1, 0, 0><<<g1, 256, SM01>>>(pxS, pW2, pUS, 1024, 1024, 1024, PX, PW, PX, 64, 1.0f, nullptr);

    // logits = Q@K^T (A normal, B normal) -> fp32 att in d_out
    gemm_bf16<0, 0, 1, 1><<<dim3(32, 32), 256, SM00>>>(pQS, pKS, att, 1024, 1024, 4096, PX, PX, 0, 64, 1.0f, nullptr);

    // softmax + fused bf16 split (row-major planes)
    softmax_split<<<n, 256>>>(att, pattB, PA);

    // rank-1 uniform-row vector from U planes
    rank1_kernel<<<8, 1024>>>(pUS, pu);

    // y = att^T @ U + u  (A=att [K][M] trans, B=U [K][N] trans) -> fp32 y_out
    gemm_bf16<1, 1, 2, 2><<<g1, 256, SM11>>>(pattB, pUS, y_out, 4096, 1024, 1024, PA, PX, 0, 256, 1.0f, pu);
}

// round 10
// speedup vs baseline: 1.3700x; 1.1475x over previous
#include <cuda_runtime.h>
#include <cuda_bf16.h>
#include <stdint.h>

#define FMAXV 3.4028235e38f

// ============================================================
// Device scratch (allocation-free). All split buffers: 2 bf16 planes
// (hi, residual) in the tensor's NATIVE layout — no transposes anywhere.
// Reassociation: y = att^T @ (x @ (WV@Wout)) + u.
// g_KS is DEAD after the logits GEMM -> reused as fp32 split-K partial (16MB).
// ============================================================
__device__ __nv_bfloat16 g_xS  [2ull*4096*1024];   // [n][m]
__device__ __nv_bfloat16 g_WKs [2ull*1024*1024];   // [m][d]
__device__ __nv_bfloat16 g_WQs [2ull*1024*1024];
__device__ __nv_bfloat16 g_WVs [2ull*1024*1024];
__device__ __nv_bfloat16 g_Wos [2ull*1024*1024];   // [d][m]
__device__ __nv_bfloat16 g_W2s [2ull*1024*1024];   // [m][m] = WV@Wout
__device__ __nv_bfloat16 g_KS  [2ull*4096*1024];   // [j][d]; later: fp32 partial
__device__ __nv_bfloat16 g_QS  [2ull*4096*1024];   // [i][d]
__device__ __nv_bfloat16 g_US  [2ull*4096*1024];   // [j][k] = x@W2
__device__ __nv_bfloat16 g_attB[2ull*4096*4096];   // [r][a] (row-major, from softmax)
__device__ float         g_u   [1024];

// ============================================================
// Helpers (base sm_103-safe: mma.sync bf16, cp.async, ldmatrix)
// ============================================================
__device__ __forceinline__ uint32_t smem_u32(const void* p) {
    uint32_t a;
    asm("{ .reg .u64 t; cvta.to.shared.u64 t, %1; cvt.u32.u64 %0, t; }" : "=r"(a) : "l"(p));
    return a;
}
__device__ __forceinline__ void cp16(void* s, const void* g) {
    uint32_t a = smem_u32(s);
    asm volatile("cp.async.cg.shared.global [%0], [%1], 16;" :: "r"(a), "l"(g));
}
#define CP_COMMIT()  asm volatile("cp.async.commit_group;" ::: "memory")
#define CP_WAIT(N)   asm volatile("cp.async.wait_group %0;" :: "n"(N) : "memory")

__device__ __forceinline__ void ldsm4(uint32_t* r, uint32_t a) {
    asm volatile("ldmatrix.sync.aligned.m8n8.x4.shared.b16 {%0,%1,%2,%3}, [%4];"
        : "=r"(r[0]), "=r"(r[1]), "=r"(r[2]), "=r"(r[3]) : "r"(a));
}
__device__ __forceinline__ void ldsm4t(uint32_t* r, uint32_t a) {
    asm volatile("ldmatrix.sync.aligned.m8n8.x4.trans.shared.b16 {%0,%1,%2,%3}, [%4];"
        : "=r"(r[0]), "=r"(r[1]), "=r"(r[2]), "=r"(r[3]) : "r"(a));
}
__device__ __forceinline__ void ldsm2(uint32_t* r, uint32_t a) {
    asm volatile("ldmatrix.sync.aligned.m8n8.x2.shared.b16 {%0,%1}, [%2];"
        : "=r"(r[0]), "=r"(r[1]) : "r"(a));
}
__device__ __forceinline__ void ldsm2t(uint32_t* r, uint32_t a) {
    asm volatile("ldmatrix.sync.aligned.m8n8.x2.trans.shared.b16 {%0,%1}, [%2];"
        : "=r"(r[0]), "=r"(r[1]) : "r"(a));
}
__device__ __forceinline__ void mma16(float* c, const uint32_t* a, const uint32_t* b) {
    asm volatile(
        "mma.sync.aligned.m16n8k16.row.col.f32.bf16.bf16.f32 "
        "{%0,%1,%2,%3}, {%4,%5,%6,%7}, {%8,%9}, {%0,%1,%2,%3};"
        : "+f"(c[0]), "+f"(c[1]), "+f"(c[2]), "+f"(c[3])
        : "r"(a[0]), "r"(a[1]), "r"(a[2]), "r"(a[3]), "r"(b[0]), "r"(b[1]));
}
__device__ __forceinline__ uint32_t split2_u32(float v0, float v1, uint32_t* lo) {
    __nv_bfloat16 h0 = __float2bfloat16_rn(v0);
    __nv_bfloat16 h1 = __float2bfloat16_rn(v1);
    __nv_bfloat16 l0 = __float2bfloat16_rn(v0 - __bfloat162float(h0));
    __nv_bfloat16 l1 = __float2bfloat16_rn(v1 - __bfloat162float(h1));
    *lo = (uint32_t)__bfloat16_as_ushort(l0) | ((uint32_t)__bfloat16_as_ushort(l1) << 16);
    return (uint32_t)__bfloat16_as_ushort(h0) | ((uint32_t)__bfloat16_as_ushort(h1) << 16);
}

// ============================================================
// GEMM (R6 core schedule): D[m,n] = sum_k A[m,k]*B[n,k].
// A,B = 2-plane bf16 split; 3 products/K16 (Ah*Bh + Ah*Bm + Am*Bh).
// Tile 128x128, BK=16, 256 thr (8 warps, 64x32), 4-stage cp.async,
// one barrier per chunk, issue() at END of loop body (LDSMs first).
// EPI: 0 = bf16 split out, 1 = fp32 out
// SKIP: 1 = fully-masked logits tile -> return, no writes
//       2 = attV: IB reversed (longest first), K-chunks j < IB-129,
//           blockIdx.z halves the chunk range; z=1 writes Cv2.
// ============================================================
template <int TRA, int TRB, int EPI, int SKIP>
__global__ void __launch_bounds__(256, 2)
gemm_bf16(const __nv_bfloat16* __restrict__ A, const __nv_bfloat16* __restrict__ B,
          void* __restrict__ Cv, int lda, int ldb, int ldc,
          long long planeA, long long planeB, long long planeC,
          int nch, float alpha, void* __restrict__ Cv2)
{
    constexpr int AROW = TRA ? 136 : 24;          // padded row strides (halves)
    constexpr int BROW = TRB ? 136 : 24;
    constexpr int APL  = TRA ? 16 * 136 : 128 * 24;
    constexpr int BPL  = TRB ? 16 * 136 : 128 * 24;
    constexpr int STG  = 2 * APL + 2 * BPL;       // Ah, Am, Bh, Bm (halves)

    const int tid = threadIdx.x;
    const int IBb = (SKIP == 2) ? (31 - blockIdx.y) : blockIdx.y;
    const int IB = IBb * 128;
    const int JB = blockIdx.x * 128;

    if (SKIP == 1 && (JB + 127 - IB) <= 256) return;

    extern __shared__ __nv_bfloat16 smh[];

    int t0 = 0, t1 = nch;
    if (SKIP == 2) {
        int n1 = IB - 129; if (n1 < 0) n1 = 0;
        int T = (n1 + 15) >> 4; if (T > nch) T = nch;
        int Th = (T + 1) >> 1;
        if (blockIdx.z == 0) { t1 = Th; }
        else                 { t0 = Th; t1 = T; Cv = Cv2; }
    }

    const int lane = tid & 31, w = tid >> 5;
    const int RW = (w >> 2) * 64, CW = (w & 3) * 32;

    // ldmatrix per-lane offsets (halves within plane)
    const int lq = lane >> 3, li = lane & 7, q2 = lq & 1;
    int aoff, boff;
    if (TRA) aoff = ((lq >> 1) * 8 + li) * AROW + RW + (lq & 1) * 8;
    else     aoff = (RW + (lq & 1) * 8 + li) * AROW + (lq >> 1) * 8;
    if (TRB) boff = (q2 * 8 + li) * BROW + CW;
    else     boff = (CW + li) * BROW + q2 * 8;
    constexpr int AMT = TRA ? 16 : 16 * AROW;     // per-mt advance
    constexpr int BNT = TRB ? 8 : 8 * BROW;       // per-nt advance
    const uint32_t sb0 = smem_u32(smh);

    auto issue = [&](int t) {
        int k0 = t * 16;
        __nv_bfloat16* sb = smh + (t & 3) * STG;
        #pragma unroll
        for (int it = 0; it < 2; it++) {          // A: 2 planes
            int idx = tid + it * 256;
            int pl = idx >> 8, r = idx & 255;
            __nv_bfloat16* dst; const __nv_bfloat16* src;
            if (TRA) { int row = r >> 4, ch = r & 15;
                dst = sb + pl * APL + row * AROW + ch * 8;
                src = A + (size_t)pl * planeA + (size_t)(k0 + row) * lda + IB + ch * 8;
            } else { int row = r >> 1, ch = r & 1;
                dst = sb + pl * APL + row * AROW + ch * 8;
                src = A + (size_t)pl * planeA + (size_t)(IB + row) * lda + k0 + ch * 8;
            }
            cp16(dst, src);
        }
        #pragma unroll
        for (int it = 0; it < 2; it++) {          // B: 2 planes
            int idx = tid + it * 256;
            int pl = idx >> 8, r = idx & 255;
            __nv_bfloat16* dst; const __nv_bfloat16* src;
            if (TRB) { int row = r >> 4, ch = r & 15;
                dst = sb + 2 * APL + pl * BPL + row * BROW + ch * 8;
                src = B + (size_t)pl * planeB + (size_t)(k0 + row) * ldb + JB + ch * 8;
            } else { int row = r >> 1, ch = r & 1;
                dst = sb + 2 * APL + pl * BPL + row * BROW + ch * 8;
                src = B + (size_t)pl * planeB + (size_t)(JB + row) * ldb + k0 + ch * 8;
            }
            cp16(dst, src);
        }
        CP_COMMIT();
    };

    float acc[64];
    #pragma unroll
    for (int i = 0; i < 64; i++) acc[i] = 0.f;

    if (t0 + 0 < t1) issue(t0 + 0);
    if (t0 + 1 < t1) issue(t0 + 1);
    if (t0 + 2 < t1) issue(t0 + 2);

    for (int t = t0; t < t1; t++) {
        if (t + 2 < t1) { CP_WAIT(2); } else if (t + 1 < t1) { CP_WAIT(1); } else { CP_WAIT(0); }
        __syncthreads();

        uint32_t sbb = sb0 + (uint32_t)((t & 3) * STG) * 2;
        uint32_t aH = sbb + (uint32_t)aoff * 2;
        uint32_t aM = aH + APL * 2;
        uint32_t bHa = sbb + (uint32_t)(2 * APL + boff) * 2;
        uint32_t bMa = bHa + BPL * 2;

        uint32_t af[16], am[16], bh[8], bm[8];
        #pragma unroll
        for (int mt = 0; mt < 4; mt++) {
            if (TRA) ldsm4t(af + mt * 4, aH + mt * AMT * 2);
            else     ldsm4 (af + mt * 4, aH + mt * AMT * 2);
        }
        #pragma unroll
        for (int nt = 0; nt < 4; nt++) {
            if (TRB) ldsm2t(bh + nt * 2, bHa + nt * BNT * 2);
            else     ldsm2 (bh + nt * 2, bHa + nt * BNT * 2);
        }
        #pragma unroll
        for (int mt = 0; mt < 4; mt++)
            #pragma unroll
            for (int nt = 0; nt < 4; nt++)
                mma16(&acc[(mt * 4 + nt) * 4], af + mt * 4, bh + nt * 2);
        #pragma unroll
        for (int nt = 0; nt < 4; nt++) {
            if (TRB) ldsm2t(bm + nt * 2, bMa + nt * BNT * 2);
            else     ldsm2 (bm + nt * 2, bMa + nt * BNT * 2);
        }
        #pragma unroll
        for (int mt = 0; mt < 4; mt++)
            #pragma unroll
            for (int nt = 0; nt < 4; nt++)
                mma16(&acc[(mt * 4 + nt) * 4], af + mt * 4, bm + nt * 2);
        #pragma unroll
        for (int mt = 0; mt < 4; mt++) {
            if (TRA) ldsm4t(am + mt * 4, aM + mt * AMT * 2);
            else     ldsm4 (am + mt * 4, aM + mt * AMT * 2);
        }
        #pragma unroll
        for (int mt = 0; mt < 4; mt++)
            #pragma unroll
            for (int nt = 0; nt < 4; nt++)
                mma16(&acc[(mt * 4 + nt) * 4], am + mt * 4, bh + nt * 2);

        if (t + 3 < t1) issue(t + 3);   // writes stage (t-1)&3, freed by top barrier
    }

    // ---------------- epilogue ----------------
    const int eg = lane >> 2, etg = lane & 3;
    #pragma unroll
    for (int mt = 0; mt < 4; mt++) {
        #pragma unroll
        for (int nt = 0; nt < 4; nt++) {
            const float* cc = &acc[(mt * 4 + nt) * 4];
            int r0 = IB + RW + mt * 16 + eg;
            int c0 = JB + CW + nt * 8 + 2 * etg;
            #pragma unroll
            for (int half = 0; half < 2; half++) {
                int r = r0 + half * 8;
                float v0 = cc[half * 2 + 0] * alpha;
                float v1 = cc[half * 2 + 1] * alpha;
                if (EPI == 1) {
                    *(float2*)((float*)Cv + (size_t)r * ldc + c0) = make_float2(v0, v1);
                } else {
                    __nv_bfloat16* dst = (__nv_bfloat16*)Cv + (size_t)r * ldc + c0;
                    uint32_t lo;
                    uint32_t hi = split2_u32(v0, v1, &lo);
                    *(uint32_t*)dst            = hi;
                    *(uint32_t*)(dst + planeC) = lo;
                }
            }
        }
    }
}

// ============================================================
// Elementwise split to 2 bf16 planes (float4 vectorized)
// ============================================================
__global__ void __launch_bounds__(256)
split_kernel(const float* __restrict__ in, __nv_bfloat16* __restrict__ out, size_t S)
{
    size_t S4 = S >> 2;
    uint32_t* oh = (uint32_t*)out;
    uint32_t* ol = (uint32_t*)(out + S);
    for (size_t i4 = (size_t)blockIdx.x * blockDim.x + threadIdx.x; i4 < S4;
         i4 += (size_t)gridDim.x * blockDim.x) {
        float4 v = ((const float4*)in)[i4];
        uint32_t l0, l1;
        uint32_t h0 = split2_u32(v.x, v.y, &l0);
        uint32_t h1 = split2_u32(v.z, v.w, &l1);
        oh[i4 * 2] = h0; oh[i4 * 2 + 1] = h1;
        ol[i4 * 2] = l0; ol[i4 * 2 + 1] = l1;
    }
}

// Fused 4-weight split: blockIdx.y selects which 1024x1024 weight.
__global__ void __launch_bounds__(256)
splitW_kernel(const float* __restrict__ w0, const float* __restrict__ w1,
              const float* __restrict__ w2, const float* __restrict__ w3,
              __nv_bfloat16* __restrict__ o0, __nv_bfloat16* __restrict__ o1,
              __nv_bfloat16* __restrict__ o2, __nv_bfloat16* __restrict__ o3)
{
    const size_t S = 1024ull * 1024;
    const float* in;
    __nv_bfloat16* out;
    switch (blockIdx.y) {
        case 0: in = w0; out = o0; break;
        case 1: in = w1; out = o1; break;
        case 2: in = w2; out = o2; break;
        default: in = w3; out = o3; break;
    }
    uint32_t* oh = (uint32_t*)out;
    uint32_t* ol = (uint32_t*)(out + S);
    size_t S4 = S >> 2;
    for (size_t i4 = (size_t)blockIdx.x * blockDim.x + threadIdx.x; i4 < S4;
         i4 += (size_t)gridDim.x * blockDim.x) {
        float4 v = ((const float4*)in)[i4];
        uint32_t l0, l1;
        uint32_t h0 = split2_u32(v.x, v.y, &l0);
        uint32_t h1 = split2_u32(v.z, v.w, &l1);
        oh[i4 * 2] = h0; oh[i4 * 2 + 1] = h1;
        ol[i4 * 2] = l0; ol[i4 * 2 + 1] = l1;
    }
}

// ============================================================
// rank-1 uniform-row correction from U bf16 planes (parallel over j):
// u[k] = (1/4096) * sum_{j>=3839} (Uh+Ul)[j][k]
// ============================================================
__global__ void __launch_bounds__(1024)
rank1_kernel(const __nv_bfloat16* __restrict__ Up, float* __restrict__ u)
{
    __shared__ float part[8][128];
    const int kl = threadIdx.x & 127;
    const int js = threadIdx.x >> 7;          // 0..7
    const int k = blockIdx.x * 128 + kl;
    const __nv_bfloat16* Uh = Up;
    const __nv_bfloat16* Ul = Up + 4096ull * 1024;
    float s = 0.f;
    for (int j = 3839 + js; j < 4096; j += 8) {
        size_t o = (size_t)j * 1024 + k;
        s += __bfloat162float(Uh[o]) + __bfloat162float(Ul[o]);
    }
    part[js][kl] = s;
    __syncthreads();
    if (threadIdx.x < 128) {
        float t = 0.f;
        #pragma unroll
        for (int q = 0; q < 8; q++) t += part[q][threadIdx.x];
        u[k] = t * (1.0f / 4096.0f);
    }
}

// ============================================================
// Combine: y[i][k] = part0(y in-place) + part1 + u[k]
// ============================================================
__global__ void __launch_bounds__(256)
combine_kernel(float* __restrict__ y, const float* __restrict__ part,
               const float* __restrict__ u)
{
    const size_t S4 = (4096ull * 1024) >> 2;
    for (size_t i4 = (size_t)blockIdx.x * blockDim.x + threadIdx.x; i4 < S4;
         i4 += (size_t)gridDim.x * blockDim.x) {
        float4 a = ((float4*)y)[i4];
        float4 b = ((const float4*)part)[i4];
        float4 uu = ((const float4*)u)[i4 & 255];   // k = (i4*4) % 1024
        a.x += b.x + uu.x; a.y += b.y + uu.y;
        a.z += b.z + uu.z; a.w += b.w + uu.w;
        ((float4*)y)[i4] = a;
    }
}

// ============================================================
// Structured softmax + fused bf16 split, one block per row.
// Row i < 3839: live cols j >= i+257; writes fp32 att row (zero head +
// normalized live) AND bf16 hi/lo planes row-major.
// Rows i >= 3839: fp32 = 1/4096 exactly, bf16 planes = 0 (rank-1 handles them).
// ============================================================
__global__ void __launch_bounds__(256)
softmax_split(float* __restrict__ att, __nv_bfloat16* __restrict__ ab, long long PA)
{
    const int i = blockIdx.x;
    const int tid = threadIdx.x;
    float* p = att + (size_t)i * 4096;
    __nv_bfloat16* bhp = ab + (size_t)i * 4096;
    __nv_bfloat16* blp = bhp + PA;

    if (i >= 3839) {
        const float c = 1.0f / 4096.0f;
        float4 cv = make_float4(c, c, c, c);
        #pragma unroll
        for (int q = 0; q < 4; q++) ((float4*)p)[tid + q * 256] = cv;
        uint4 z = make_uint4(0, 0, 0, 0);
        #pragma unroll
        for (int q = 0; q < 2; q++) {
            ((uint4*)bhp)[tid + q * 256] = z;
            ((uint4*)blp)[tid + q * 256] = z;
        }
        return;
    }

    const int start = i + 257;
    const int s16 = start & ~15;
    const int nv4 = (4096 - s16) >> 2;
    float4* live = (float4*)(p + s16);

    float4 v[4];
    float mx = -FMAXV;
    #pragma unroll
    for (int q = 0; q < 4; q++) {
        int i4 = tid + q * 256;
        if (i4 < nv4) {
            float4 tv = live[i4];
            int j0 = s16 + i4 * 4;
            if (j0 < start) {
                if (j0 + 0 < start) tv.x = -FMAXV;
                if (j0 + 1 < start) tv.y = -FMAXV;
                if (j0 + 2 < start) tv.z = -FMAXV;
                if (j0 + 3 < start) tv.w = -FMAXV;
            }
            v[q] = tv;
            mx = fmaxf(mx, fmaxf(fmaxf(tv.x, tv.y), fmaxf(tv.z, tv.w)));
        }
    }
    #pragma unroll
    for (int o = 16; o > 0; o >>= 1) mx = fmaxf(mx, __shfl_xor_sync(0xffffffffu, mx, o));
    __shared__ float red[8];
    if ((tid & 31) == 0) red[tid >> 5] = mx;
    __syncthreads();
    mx = red[0];
    #pragma unroll
    for (int ww = 1; ww < 8; ww++) mx = fmaxf(mx, red[ww]);
    __syncthreads();

    float s = 0.f;
    #pragma unroll
    for (int q = 0; q < 4; q++) {
        if (tid + q * 256 < nv4) {
            v[q].x = expf(v[q].x - mx); s += v[q].x;
            v[q].y = expf(v[q].y - mx); s += v[q].y;
            v[q].z = expf(v[q].z - mx); s += v[q].z;
            v[q].w = expf(v[q].w - mx); s += v[q].w;
        }
    }
    #pragma unroll
    for (int o = 16; o > 0; o >>= 1) s += __shfl_xor_sync(0xffffffffu, s, o);
    if ((tid & 31) == 0) red[tid >> 5] = s;
    __syncthreads();
    s = red[0];
    #pragma unroll
    for (int ww = 1; ww < 8; ww++) s += red[ww];

    float inv = 1.0f / s;
    uint2* bhl = (uint2*)(bhp + s16);
    uint2* bll = (uint2*)(blp + s16);
    #pragma unroll
    for (int q = 0; q < 4; q++) {
        int i4 = tid + q * 256;
        if (i4 < nv4) {
            v[q].x *= inv; v[q].y *= inv; v[q].z *= inv; v[q].w *= inv;
            live[i4] = v[q];
            uint32_t l0, l1;
            uint32_t h0 = split2_u32(v[q].x, v[q].y, &l0);
            uint32_t h1 = split2_u32(v[q].z, v[q].w, &l1);
            bhl[i4] = make_uint2(h0, h1);
            bll[i4] = make_uint2(l0, l1);
        }
    }
    // zero heads
    float4 z4 = make_float4(0.f, 0.f, 0.f, 0.f);
    int nz4 = s16 >> 2;
    for (int i4 = tid; i4 < nz4; i4 += 256) ((float4*)p)[i4] = z4;
    uint2 z2 = make_uint2(0, 0);
    for (int i2 = tid; i2 < nz4; i2 += 256) {
        ((uint2*)bhp)[i2] = z2;
        ((uint2*)blp)[i2] = z2;
    }
}

// ============================================================
// Host
// ============================================================
extern "C" void kernel_launch(void* const* d_in, const int* in_sizes, int n_in,
                              void* d_out, int out_size)
{
    const float* x    = (const float*)d_in[0];
    const float* WK   = (const float*)d_in[1];
    const float* WQ   = (const float*)d_in[2];
    const float* WV   = (const float*)d_in[3];
    const float* Wout = (const float*)d_in[4];

    const int m = 1024;
    const int n = in_sizes[0] / m;   // 4096

    float* y_out = (float*)d_out;                 // [n, m]
    float* att   = y_out + (size_t)n * m;         // [n, n]

    __nv_bfloat16 *pxS, *pWK, *pWQ, *pWV, *pWo, *pW2, *pKS, *pQS, *pUS, *pattB;
    float* pu;
    cudaGetSymbolAddress((void**)&pxS,  g_xS);
    cudaGetSymbolAddress((void**)&pWK,  g_WKs);
    cudaGetSymbolAddress((void**)&pWQ,  g_WQs);
    cudaGetSymbolAddress((void**)&pWV,  g_WVs);
    cudaGetSymbolAddress((void**)&pWo,  g_Wos);
    cudaGetSymbolAddress((void**)&pW2,  g_W2s);
    cudaGetSymbolAddress((void**)&pKS,  g_KS);
    cudaGetSymbolAddress((void**)&pQS,  g_QS);
    cudaGetSymbolAddress((void**)&pUS,  g_US);
    cudaGetSymbolAddress((void**)&pattB, g_attB);
    cudaGetSymbolAddress((void**)&pu,   g_u);
    float* ppart = (float*)pKS;   // g_KS reused as fp32 partial after logits

    // dynamic smem per instantiation (4 stages)
    const int SM01 = 4 * (2 * (128 * 24) + 2 * (16 * 136)) * 2;  // 83968
    const int SM00 = 4 * (4 * (128 * 24)) * 2;                   // 98304
    const int SM11 = 4 * (4 * (16 * 136)) * 2;                   // 69632

    cudaFuncSetAttribute(gemm_bf16<0, 1, 0, 0>, cudaFuncAttributeMaxDynamicSharedMemorySize, SM01);
    cudaFuncSetAttribute(gemm_bf16<0, 0, 1, 1>, cudaFuncAttributeMaxDynamicSharedMemorySize, SM00);
    cudaFuncSetAttribute(gemm_bf16<1, 1, 1, 2>, cudaFuncAttributeMaxDynamicSharedMemorySize, SM11);

    const long long PX = 4096LL * 1024;
    const long long PW = 1024LL * 1024;
    const long long PA = 4096LL * 4096;

    // Elementwise splits only — NO transposes. Weights fused in one launch.
    split_kernel<<<2048, 256>>>(x, pxS, (size_t)n * m);
    splitW_kernel<<<dim3(512, 4), 256>>>(WK, WQ, WV, Wout, pWK, pWQ, pWV, pWo);

    dim3 g1(8, 32);
    // K = x@WK, Q = 0.06*(x@WQ)  (A normal, B=[K][N] trans) -> bf16 split
    gemm_bf16<0, 1, 0, 0><<<g1, 256, SM01>>>(pxS, pWK, pKS, 1024, 1024, 1024, PX, PW, PX, 64, 1.0f, nullptr);
    gemm_bf16<0, 1, 0, 0><<<g1, 256, SM01>>>(pxS, pWQ, pQS, 1024, 1024, 1024, PX, PW, PX, 64, 0.06f, nullptr);

    // W2 = WV@Wout -> bf16 split; U = x@W2 -> bf16 split
    gemm_bf16<0, 1, 0, 0><<<dim3(8, 8), 256, SM01>>>(pWV, pWo, pW2, 1024, 1024, 1024, PW, PW, PW, 64, 1.0f, nullptr);
    gemm_bf16<0, 1, 0, 0><<<g1, 256, SM01>>>(pxS, pW2, pUS, 1024, 1024, 1024, PX, PW, PX, 64, 1.0f, nullptr);

    // logits = Q@K^T (A normal, B normal) -> fp32 att in d_out
    gemm_bf16<0, 0, 1, 1><<<dim3(32, 32), 256, SM00>>>(pQS, pKS, att, 1024, 1024, 4096, PX, PX, 0, 64, 1.0f, nullptr);

    // softmax + fused bf16 split (row-major planes)
    softmax_split<<<n, 256>>>(att, pattB, PA);

    // rank-1 uniform-row vector from U planes
    rank1_kernel<<<8, 1024>>>(pUS, pu);

    // y_partial = att^T @ U  (split-K x2, longest-first; z=0 -> y_out, z=1 -> part)
    gemm_bf16<1, 1, 1, 2><<<dim3(8, 32, 2), 256, SM11>>>(pattB, pUS, y_out, 4096, 1024, 1024, PA, PX, 0, 256, 1.0f, ppart);

    // y = y + part + u
    combine_kernel<<<2048, 256>>>(y_out, ppart, pu);
}

// round 12
// speedup vs baseline: 1.3866x; 1.0121x over previous
#include <cuda_runtime.h>
#include <cuda_bf16.h>
#include <stdint.h>

#define FMAXV 3.4028235e38f

// ============================================================
// Device scratch (allocation-free). All split buffers: 2 bf16 planes
// (hi, residual) in the tensor's NATIVE layout — no transposes anywhere.
// Reassociation: y = att^T @ (x @ (WV@Wout)) + u.
// g_KS is DEAD after the logits GEMM -> reused as fp32 split-K partial (16MB).
// ============================================================
__device__ __nv_bfloat16 g_xS  [2ull*4096*1024];   // [n][m]
__device__ __nv_bfloat16 g_WKs [2ull*1024*1024];   // [m][d]
__device__ __nv_bfloat16 g_WQs [2ull*1024*1024];
__device__ __nv_bfloat16 g_WVs [2ull*1024*1024];
__device__ __nv_bfloat16 g_Wos [2ull*1024*1024];   // [d][m]
__device__ __nv_bfloat16 g_W2s [2ull*1024*1024];   // [m][m] = WV@Wout
__device__ __nv_bfloat16 g_KS  [2ull*4096*1024];   // [j][d]; later: fp32 partial
__device__ __nv_bfloat16 g_QS  [2ull*4096*1024];   // [i][d]
__device__ __nv_bfloat16 g_US  [2ull*4096*1024];   // [j][k] = x@W2
__device__ __nv_bfloat16 g_attB[2ull*4096*4096];   // [r][a] (row-major, from softmax)
__device__ float         g_u   [1024];

// ============================================================
// Helpers (base sm_103-safe: mma.sync bf16, cp.async, ldmatrix)
// ============================================================
__device__ __forceinline__ uint32_t smem_u32(const void* p) {
    uint32_t a;
    asm("{ .reg .u64 t; cvta.to.shared.u64 t, %1; cvt.u32.u64 %0, t; }" : "=r"(a) : "l"(p));
    return a;
}
__device__ __forceinline__ void cp16(void* s, const void* g) {
    uint32_t a = smem_u32(s);
    asm volatile("cp.async.cg.shared.global [%0], [%1], 16;" :: "r"(a), "l"(g));
}
#define CP_COMMIT()  asm volatile("cp.async.commit_group;" ::: "memory")
#define CP_WAIT(N)   asm volatile("cp.async.wait_group %0;" :: "n"(N) : "memory")

__device__ __forceinline__ void ldsm4(uint32_t* r, uint32_t a) {
    asm volatile("ldmatrix.sync.aligned.m8n8.x4.shared.b16 {%0,%1,%2,%3}, [%4];"
        : "=r"(r[0]), "=r"(r[1]), "=r"(r[2]), "=r"(r[3]) : "r"(a));
}
__device__ __forceinline__ void ldsm4t(uint32_t* r, uint32_t a) {
    asm volatile("ldmatrix.sync.aligned.m8n8.x4.trans.shared.b16 {%0,%1,%2,%3}, [%4];"
        : "=r"(r[0]), "=r"(r[1]), "=r"(r[2]), "=r"(r[3]) : "r"(a));
}
__device__ __forceinline__ void ldsm2(uint32_t* r, uint32_t a) {
    asm volatile("ldmatrix.sync.aligned.m8n8.x2.shared.b16 {%0,%1}, [%2];"
        : "=r"(r[0]), "=r"(r[1]) : "r"(a));
}
__device__ __forceinline__ void ldsm2t(uint32_t* r, uint32_t a) {
    asm volatile("ldmatrix.sync.aligned.m8n8.x2.trans.shared.b16 {%0,%1}, [%2];"
        : "=r"(r[0]), "=r"(r[1]) : "r"(a));
}
__device__ __forceinline__ void mma16(float* c, const uint32_t* a, const uint32_t* b) {
    asm volatile(
        "mma.sync.aligned.m16n8k16.row.col.f32.bf16.bf16.f32 "
        "{%0,%1,%2,%3}, {%4,%5,%6,%7}, {%8,%9}, {%0,%1,%2,%3};"
        : "+f"(c[0]), "+f"(c[1]), "+f"(c[2]), "+f"(c[3])
        : "r"(a[0]), "r"(a[1]), "r"(a[2]), "r"(a[3]), "r"(b[0]), "r"(b[1]));
}
__device__ __forceinline__ uint32_t split2_u32(float v0, float v1, uint32_t* lo) {
    __nv_bfloat16 h0 = __float2bfloat16_rn(v0);
    __nv_bfloat16 h1 = __float2bfloat16_rn(v1);
    __nv_bfloat16 l0 = __float2bfloat16_rn(v0 - __bfloat162float(h0));
    __nv_bfloat16 l1 = __float2bfloat16_rn(v1 - __bfloat162float(h1));
    *lo = (uint32_t)__bfloat16_as_ushort(l0) | ((uint32_t)__bfloat16_as_ushort(l1) << 16);
    return (uint32_t)__bfloat16_as_ushort(h0) | ((uint32_t)__bfloat16_as_ushort(h1) << 16);
}

// ============================================================
// GEMM (R6 core schedule, BK/NS templated): D[m,n] = sum_k A[m,k]*B[n,k].
// A,B = 2-plane bf16 split; 3 products/K16 (Ah*Bh + Ah*Bm + Am*Bh).
// Tile 128x128, 256 thr (8 warps, 64x32), NS-stage cp.async,
// one barrier per BK-chunk, issue() at END of loop body (LDSMs first).
// BK=16/NS=4 (proven logits config) or BK=32/NS=3 (half the barriers).
// Non-trans smem row stride = BK+8 halves (16B-aligned rows, conflict-free).
// EPI: 0 = bf16 split out, 1 = fp32 out
// SKIP: 1 = fully-masked logits tile -> return, no writes
//       2 = attV: IB reversed (longest first), K-chunks j < IB-129,
//           blockIdx.z halves the chunk range; z=1 writes Cv2.
// ============================================================
template <int TRA, int TRB, int EPI, int SKIP, int BK, int NS>
__global__ void __launch_bounds__(256, 2)
gemm_bf16(const __nv_bfloat16* __restrict__ A, const __nv_bfloat16* __restrict__ B,
          void* __restrict__ Cv, int lda, int ldb, int ldc,
          long long planeA, long long planeB, long long planeC,
          int nch, float alpha, void* __restrict__ Cv2)
{
    constexpr int AROW = TRA ? 136 : (BK + 8);    // padded row strides (halves)
    constexpr int BROW = TRB ? 136 : (BK + 8);
    constexpr int APL  = TRA ? BK * 136 : 128 * (BK + 8);
    constexpr int BPL  = TRB ? BK * 136 : 128 * (BK + 8);
    constexpr int STG  = 2 * APL + 2 * BPL;       // Ah, Am, Bh, Bm (halves)
    constexpr int KSN  = BK / 16;                 // k16 sub-chunks per chunk

    const int tid = threadIdx.x;
    const int IBb = (SKIP == 2) ? (31 - blockIdx.y) : blockIdx.y;
    const int IB = IBb * 128;
    const int JB = blockIdx.x * 128;

    if (SKIP == 1 && (JB + 127 - IB) <= 256) return;

    extern __shared__ __nv_bfloat16 smh[];

    int t0 = 0, t1 = nch;
    if (SKIP == 2) {
        int n1 = IB - 129; if (n1 < 0) n1 = 0;
        int T = (n1 + BK - 1) / BK; if (T > nch) T = nch;
        int Th = (T + 1) >> 1;
        if (blockIdx.z == 0) { t1 = Th; }
        else                 { t0 = Th; t1 = T; Cv = Cv2; }
    }

    const int lane = tid & 31, w = tid >> 5;
    const int RW = (w >> 2) * 64, CW = (w & 3) * 32;

    // ldmatrix per-lane offsets (halves within plane)
    const int lq = lane >> 3, li = lane & 7, q2 = lq & 1;
    int aoff, boff;
    if (TRA) aoff = ((lq >> 1) * 8 + li) * AROW + RW + (lq & 1) * 8;
    else     aoff = (RW + (lq & 1) * 8 + li) * AROW + (lq >> 1) * 8;
    if (TRB) boff = (q2 * 8 + li) * BROW + CW;
    else     boff = (CW + li) * BROW + q2 * 8;
    constexpr int AMT = TRA ? 16 : 16 * AROW;     // per-mt advance
    constexpr int BNT = TRB ? 8 : 8 * BROW;       // per-nt advance
    constexpr int AKS = TRA ? 16 * 136 : 16;      // per-k16 advance
    constexpr int BKS = TRB ? 16 * 136 : 16;
    const uint32_t sb0 = smem_u32(smh);

    auto issue = [&](int t) {
        int k0 = t * BK;
        __nv_bfloat16* sb = smh + (t % NS) * STG;
        constexpr int APPL = TRA ? BK * 16 : 128 * (BK / 8);  // cp16 per A plane
        constexpr int AIT  = (2 * APPL) / 256;
        #pragma unroll
        for (int it = 0; it < AIT; it++) {
            int idx = tid + it * 256;
            int pl = idx / APPL, r = idx % APPL;
            __nv_bfloat16* dst; const __nv_bfloat16* src;
            if (TRA) { int row = r >> 4, ch = r & 15;
                dst = sb + pl * APL + row * AROW + ch * 8;
                src = A + (size_t)pl * planeA + (size_t)(k0 + row) * lda + IB + ch * 8;
            } else { int row = r / (BK / 8), ch = r % (BK / 8);
                dst = sb + pl * APL + row * AROW + ch * 8;
                src = A + (size_t)pl * planeA + (size_t)(IB + row) * lda + k0 + ch * 8;
            }
            cp16(dst, src);
        }
        constexpr int BPPL = TRB ? BK * 16 : 128 * (BK / 8);
        constexpr int BIT  = (2 * BPPL) / 256;
        #pragma unroll
        for (int it = 0; it < BIT; it++) {
            int idx = tid + it * 256;
            int pl = idx / BPPL, r = idx % BPPL;
            __nv_bfloat16* dst; const __nv_bfloat16* src;
            if (TRB) { int row = r >> 4, ch = r & 15;
                dst = sb + 2 * APL + pl * BPL + row * BROW + ch * 8;
                src = B + (size_t)pl * planeB + (size_t)(k0 + row) * ldb + JB + ch * 8;
            } else { int row = r / (BK / 8), ch = r % (BK / 8);
                dst = sb + 2 * APL + pl * BPL + row * BROW + ch * 8;
                src = B + (size_t)pl * planeB + (size_t)(JB + row) * ldb + k0 + ch * 8;
            }
            cp16(dst, src);
        }
        CP_COMMIT();
    };

    float acc[64];
    #pragma unroll
    for (int i = 0; i < 64; i++) acc[i] = 0.f;

    #pragma unroll
    for (int p = 0; p < NS - 1; p++)
        if (t0 + p < t1) issue(t0 + p);

    for (int t = t0; t < t1; t++) {
        if (NS == 4) {
            if (t + 2 < t1) { CP_WAIT(2); } else if (t + 1 < t1) { CP_WAIT(1); } else { CP_WAIT(0); }
        } else {
            if (t + 1 < t1) { CP_WAIT(1); } else { CP_WAIT(0); }
        }
        __syncthreads();

        uint32_t sbb = sb0 + (uint32_t)((t % NS) * STG) * 2;

        #pragma unroll
        for (int ks = 0; ks < KSN; ks++) {
            uint32_t aH = sbb + (uint32_t)(aoff + ks * AKS) * 2;
            uint32_t aM = aH + APL * 2;
            uint32_t bHa = sbb + (uint32_t)(2 * APL + boff + ks * BKS) * 2;
            uint32_t bMa = bHa + BPL * 2;

            uint32_t af[16], am[16], bh[8], bm[8];
            #pragma unroll
            for (int mt = 0; mt < 4; mt++) {
                if (TRA) ldsm4t(af + mt * 4, aH + mt * AMT * 2);
                else     ldsm4 (af + mt * 4, aH + mt * AMT * 2);
            }
            #pragma unroll
            for (int nt = 0; nt < 4; nt++) {
                if (TRB) ldsm2t(bh + nt * 2, bHa + nt * BNT * 2);
                else     ldsm2 (bh + nt * 2, bHa + nt * BNT * 2);
            }
            #pragma unroll
            for (int mt = 0; mt < 4; mt++)
                #pragma unroll
                for (int nt = 0; nt < 4; nt++)
                    mma16(&acc[(mt * 4 + nt) * 4], af + mt * 4, bh + nt * 2);
            #pragma unroll
            for (int nt = 0; nt < 4; nt++) {
                if (TRB) ldsm2t(bm + nt * 2, bMa + nt * BNT * 2);
                else     ldsm2 (bm + nt * 2, bMa + nt * BNT * 2);
            }
            #pragma unroll
            for (int mt = 0; mt < 4; mt++)
                #pragma unroll
                for (int nt = 0; nt < 4; nt++)
                    mma16(&acc[(mt * 4 + nt) * 4], af + mt * 4, bm + nt * 2);
            #pragma unroll
            for (int mt = 0; mt < 4; mt++) {
                if (TRA) ldsm4t(am + mt * 4, aM + mt * AMT * 2);
                else     ldsm4 (am + mt * 4, aM + mt * AMT * 2);
            }
            #pragma unroll
            for (int mt = 0; mt < 4; mt++)
                #pragma unroll
                for (int nt = 0; nt < 4; nt++)
                    mma16(&acc[(mt * 4 + nt) * 4], am + mt * 4, bh + nt * 2);
        }

        if (t + NS - 1 < t1) issue(t + NS - 1);   // writes stage (t-1)%NS, freed by top barrier
    }

    // ---------------- epilogue ----------------
    const int eg = lane >> 2, etg = lane & 3;
    #pragma unroll
    for (int mt = 0; mt < 4; mt++) {
        #pragma unroll
        for (int nt = 0; nt < 4; nt++) {
            const float* cc = &acc[(mt * 4 + nt) * 4];
            int r0 = IB + RW + mt * 16 + eg;
            int c0 = JB + CW + nt * 8 + 2 * etg;
            #pragma unroll
            for (int half = 0; half < 2; half++) {
                int r = r0 + half * 8;
                float v0 = cc[half * 2 + 0] * alpha;
                float v1 = cc[half * 2 + 1] * alpha;
                if (EPI == 1) {
                    *(float2*)((float*)Cv + (size_t)r * ldc + c0) = make_float2(v0, v1);
                } else {
                    __nv_bfloat16* dst = (__nv_bfloat16*)Cv + (size_t)r * ldc + c0;
                    uint32_t lo;
                    uint32_t hi = split2_u32(v0, v1, &lo);
                    *(uint32_t*)dst            = hi;
                    *(uint32_t*)(dst + planeC) = lo;
                }
            }
        }
    }
}

// ============================================================
// Elementwise split to 2 bf16 planes (float4 vectorized)
// ============================================================
__global__ void __launch_bounds__(256)
split_kernel(const float* __restrict__ in, __nv_bfloat16* __restrict__ out, size_t S)
{
    size_t S4 = S >> 2;
    uint32_t* oh = (uint32_t*)out;
    uint32_t* ol = (uint32_t*)(out + S);
    for (size_t i4 = (size_t)blockIdx.x * blockDim.x + threadIdx.x; i4 < S4;
         i4 += (size_t)gridDim.x * blockDim.x) {
        float4 v = ((const float4*)in)[i4];
        uint32_t l0, l1;
        uint32_t h0 = split2_u32(v.x, v.y, &l0);
        uint32_t h1 = split2_u32(v.z, v.w, &l1);
        oh[i4 * 2] = h0; oh[i4 * 2 + 1] = h1;
        ol[i4 * 2] = l0; ol[i4 * 2 + 1] = l1;
    }
}

// Fused 4-weight split: blockIdx.y selects which 1024x1024 weight.
__global__ void __launch_bounds__(256)
splitW_kernel(const float* __restrict__ w0, const float* __restrict__ w1,
              const float* __restrict__ w2, const float* __restrict__ w3,
              __nv_bfloat16* __restrict__ o0, __nv_bfloat16* __restrict__ o1,
              __nv_bfloat16* __restrict__ o2, __nv_bfloat16* __restrict__ o3)
{
    const size_t S = 1024ull * 1024;
    const float* in;
    __nv_bfloat16* out;
    switch (blockIdx.y) {
        case 0: in = w0; out = o0; break;
        case 1: in = w1; out = o1; break;
        case 2: in = w2; out = o2; break;
        default: in = w3; out = o3; break;
    }
    uint32_t* oh = (uint32_t*)out;
    uint32_t* ol = (uint32_t*)(out + S);
    size_t S4 = S >> 2;
    for (size_t i4 = (size_t)blockIdx.x * blockDim.x + threadIdx.x; i4 < S4;
         i4 += (size_t)gridDim.x * blockDim.x) {
        float4 v = ((const float4*)in)[i4];
        uint32_t l0, l1;
        uint32_t h0 = split2_u32(v.x, v.y, &l0);
        uint32_t h1 = split2_u32(v.z, v.w, &l1);
        oh[i4 * 2] = h0; oh[i4 * 2 + 1] = h1;
        ol[i4 * 2] = l0; ol[i4 * 2 + 1] = l1;
    }
}

// ============================================================
// rank-1 uniform-row correction from U bf16 planes (parallel over j):
// u[k] = (1/4096) * sum_{j>=3839} (Uh+Ul)[j][k]
// ============================================================
__global__ void __launch_bounds__(1024)
rank1_kernel(const __nv_bfloat16* __restrict__ Up, float* __restrict__ u)
{
    __shared__ float part[8][128];
    const int kl = threadIdx.x & 127;
    const int js = threadIdx.x >> 7;          // 0..7
    const int k = blockIdx.x * 128 + kl;
    const __nv_bfloat16* Uh = Up;
    const __nv_bfloat16* Ul = Up + 4096ull * 1024;
    float s = 0.f;
    for (int j = 3839 + js; j < 4096; j += 8) {
        size_t o = (size_t)j * 1024 + k;
        s += __bfloat162float(Uh[o]) + __bfloat162float(Ul[o]);
    }
    part[js][kl] = s;
    __syncthreads();
    if (threadIdx.x < 128) {
        float t = 0.f;
        #pragma unroll
        for (int q = 0; q < 8; q++) t += part[q][threadIdx.x];
        u[k] = t * (1.0f / 4096.0f);
    }
}

// ============================================================
// Combine: y[i][k] = part0(y in-place) + part1 + u[k]
// ============================================================
__global__ void __launch_bounds__(256)
combine_kernel(float* __restrict__ y, const float* __restrict__ part,
               const float* __restrict__ u)
{
    const size_t S4 = (4096ull * 1024) >> 2;
    for (size_t i4 = (size_t)blockIdx.x * blockDim.x + threadIdx.x; i4 < S4;
         i4 += (size_t)gridDim.x * blockDim.x) {
        float4 a = ((float4*)y)[i4];
        float4 b = ((const float4*)part)[i4];
        float4 uu = ((const float4*)u)[i4 & 255];   // k = (i4*4) % 1024
        a.x += b.x + uu.x; a.y += b.y + uu.y;
        a.z += b.z + uu.z; a.w += b.w + uu.w;
        ((float4*)y)[i4] = a;
    }
}

// ============================================================
// Structured softmax + fused bf16 split, one block per row.
// Row i < 3839: live cols j >= i+257; writes fp32 att row (zero head +
// normalized live) AND bf16 hi/lo planes row-major.
// Rows i >= 3839: fp32 = 1/4096 exactly, bf16 planes = 0 (rank-1 handles them).
// ============================================================
__global__ void __launch_bounds__(256)
softmax_split(float* __restrict__ att, __nv_bfloat16* __restrict__ ab, long long PA)
{
    const int i = blockIdx.x;
    const int tid = threadIdx.x;
    float* p = att + (size_t)i * 4096;
    __nv_bfloat16* bhp = ab + (size_t)i * 4096;
    __nv_bfloat16* blp = bhp + PA;

    if (i >= 3839) {
        const float c = 1.0f / 4096.0f;
        float4 cv = make_float4(c, c, c, c);
        #pragma unroll
        for (int q = 0; q < 4; q++) ((float4*)p)[tid + q * 256] = cv;
        uint4 z = make_uint4(0, 0, 0, 0);
        #pragma unroll
        for (int q = 0; q < 2; q++) {
            ((uint4*)bhp)[tid + q * 256] = z;
            ((uint4*)blp)[tid + q * 256] = z;
        }
        return;
    }

    const int start = i + 257;
    const int s16 = start & ~15;
    const int nv4 = (4096 - s16) >> 2;
    float4* live = (float4*)(p + s16);

    float4 v[4];
    float mx = -FMAXV;
    #pragma unroll
    for (int q = 0; q < 4; q++) {
        int i4 = tid + q * 256;
        if (i4 < nv4) {
            float4 tv = live[i4];
            int j0 = s16 + i4 * 4;
            if (j0 < start) {
                if (j0 + 0 < start) tv.x = -FMAXV;
                if (j0 + 1 < start) tv.y = -FMAXV;
                if (j0 + 2 < start) tv.z = -FMAXV;
                if (j0 + 3 < start) tv.w = -FMAXV;
            }
            v[q] = tv;
            mx = fmaxf(mx, fmaxf(fmaxf(tv.x, tv.y), fmaxf(tv.z, tv.w)));
        }
    }
    #pragma unroll
    for (int o = 16; o > 0; o >>= 1) mx = fmaxf(mx, __shfl_xor_sync(0xffffffffu, mx, o));
    __shared__ float red[8];
    if ((tid & 31) == 0) red[tid >> 5] = mx;
    __syncthreads();
    mx = red[0];
    #pragma unroll
    for (int ww = 1; ww < 8; ww++) mx = fmaxf(mx, red[ww]);
    __syncthreads();

    float s = 0.f;
    #pragma unroll
    for (int q = 0; q < 4; q++) {
        if (tid + q * 256 < nv4) {
            v[q].x = expf(v[q].x - mx); s += v[q].x;
            v[q].y = expf(v[q].y - mx); s += v[q].y;
            v[q].z = expf(v[q].z - mx); s += v[q].z;
            v[q].w = expf(v[q].w - mx); s += v[q].w;
        }
    }
    #pragma unroll
    for (int o = 16; o > 0; o >>= 1) s += __shfl_xor_sync(0xffffffffu, s, o);
    if ((tid & 31) == 0) red[tid >> 5] = s;
    __syncthreads();
    s = red[0];
    #pragma unroll
    for (int ww = 1; ww < 8; ww++) s += red[ww];

    float inv = 1.0f / s;
    uint2* bhl = (uint2*)(bhp + s16);
    uint2* bll = (uint2*)(blp + s16);
    #pragma unroll
    for (int q = 0; q < 4; q++) {
        int i4 = tid + q * 256;
        if (i4 < nv4) {
            v[q].x *= inv; v[q].y *= inv; v[q].z *= inv; v[q].w *= inv;
            live[i4] = v[q];
            uint32_t l0, l1;
            uint32_t h0 = split2_u32(v[q].x, v[q].y, &l0);
            uint32_t h1 = split2_u32(v[q].z, v[q].w, &l1);
            bhl[i4] = make_uint2(h0, h1);
            bll[i4] = make_uint2(l0, l1);
        }
    }
    // zero heads
    float4 z4 = make_float4(0.f, 0.f, 0.f, 0.f);
    int nz4 = s16 >> 2;
    for (int i4 = tid; i4 < nz4; i4 += 256) ((float4*)p)[i4] = z4;
    uint2 z2 = make_uint2(0, 0);
    for (int i2 = tid; i2 < nz4; i2 += 256) {
        ((uint2*)bhp)[i2] = z2;
        ((uint2*)blp)[i2] = z2;
    }
}

// ============================================================
// Host
// ============================================================
extern "C" void kernel_launch(void* const* d_in, const int* in_sizes, int n_in,
                              void* d_out, int out_size)
{
    const float* x    = (const float*)d_in[0];
    const float* WK   = (const float*)d_in[1];
    const float* WQ   = (const float*)d_in[2];
    const float* WV   = (const float*)d_in[3];
    const float* Wout = (const float*)d_in[4];

    const int m = 1024;
    const int n = in_sizes[0] / m;   // 4096

    float* y_out = (float*)d_out;                 // [n, m]
    float* att   = y_out + (size_t)n * m;         // [n, n]

    __nv_bfloat16 *pxS, *pWK, *pWQ, *pWV, *pWo, *pW2, *pKS, *pQS, *pUS, *pattB;
    float* pu;
    cudaGetSymbolAddress((void**)&pxS,  g_xS);
    cudaGetSymbolAddress((void**)&pWK,  g_WKs);
    cudaGetSymbolAddress((void**)&pWQ,  g_WQs);
    cudaGetSymbolAddress((void**)&pWV,  g_WVs);
    cudaGetSymbolAddress((void**)&pWo,  g_Wos);
    cudaGetSymbolAddress((void**)&pW2,  g_W2s);
    cudaGetSymbolAddress((void**)&pKS,  g_KS);
    cudaGetSymbolAddress((void**)&pQS,  g_QS);
    cudaGetSymbolAddress((void**)&pUS,  g_US);
    cudaGetSymbolAddress((void**)&pattB, g_attB);
    cudaGetSymbolAddress((void**)&pu,   g_u);
    float* ppart = (float*)pKS;   // g_KS reused as fp32 partial after logits

    // dynamic smem per instantiation
    const int SM01 = 3 * (2 * (128 * 40) + 2 * (32 * 136)) * 2;  // BK32/NS3: 113664
    const int SM00 = 4 * (4 * (128 * 24)) * 2;                   // BK16/NS4: 98304
    const int SM11 = 3 * (4 * (32 * 136)) * 2;                   // BK32/NS3: 104448

    cudaFuncSetAttribute(gemm_bf16<0, 1, 0, 0, 32, 3>, cudaFuncAttributeMaxDynamicSharedMemorySize, SM01);
    cudaFuncSetAttribute(gemm_bf16<0, 0, 1, 1, 16, 4>, cudaFuncAttributeMaxDynamicSharedMemorySize, SM00);
    cudaFuncSetAttribute(gemm_bf16<1, 1, 1, 2, 32, 3>, cudaFuncAttributeMaxDynamicSharedMemorySize, SM11);

    const long long PX = 4096LL * 1024;
    const long long PW = 1024LL * 1024;
    const long long PA = 4096LL * 4096;

    // Elementwise splits only — NO transposes. Weights fused in one launch.
    split_kernel<<<2048, 256>>>(x, pxS, (size_t)n * m);
    splitW_kernel<<<dim3(512, 4), 256>>>(WK, WQ, WV, Wout, pWK, pWQ, pWV, pWo);

    dim3 g1(8, 32);
    // K = x@WK, Q = 0.06*(x@WQ)  (A normal, B=[K][N] trans) -> bf16 split
    gemm_bf16<0, 1, 0, 0, 32, 3><<<g1, 256, SM01>>>(pxS, pWK, pKS, 1024, 1024, 1024, PX, PW, PX, 32, 1.0f, nullptr);
    gemm_bf16<0, 1, 0, 0, 32, 3><<<g1, 256, SM01>>>(pxS, pWQ, pQS, 1024, 1024, 1024, PX, PW, PX, 32, 0.06f, nullptr);

    // W2 = WV@Wout -> bf16 split; U = x@W2 -> bf16 split
    gemm_bf16<0, 1, 0, 0, 32, 3><<<dim3(8, 8), 256, SM01>>>(pWV, pWo, pW2, 1024, 1024, 1024, PW, PW, PW, 32, 1.0f, nullptr);
    gemm_bf16<0, 1, 0, 0, 32, 3><<<g1, 256, SM01>>>(pxS, pW2, pUS, 1024, 1024, 1024, PX, PW, PX, 32, 1.0f, nullptr);

    // logits = Q@K^T (A normal, B normal, BK16/NS4 proven config) -> fp32 att
    gemm_bf16<0, 0, 1, 1, 16, 4><<<dim3(32, 32), 256, SM00>>>(pQS, pKS, att, 1024, 1024, 4096, PX, PX, 0, 64, 1.0f, nullptr);

    // softmax + fused bf16 split (row-major planes)
    softmax_split<<<n, 256>>>(att, pattB, PA);

    // rank-1 uniform-row vector from U planes
    rank1_kernel<<<8, 1024>>>(pUS, pu);

    // y_partial = att^T @ U  (split-K x2, longest-first; z=0 -> y_out, z=1 -> part)
    gemm_bf16<1, 1, 1, 2, 32, 3><<<dim3(8, 32, 2), 256, SM11>>>(pattB, pUS, y_out, 4096, 1024, 1024, PA, PX, 0, 128, 1.0f, ppart);

    // y = y + part + u
    combine_kernel<<<2048, 256>>>(y_out, ppart, pu);
}

// round 13
// speedup vs baseline: 1.3918x; 1.0038x over previous
#include <cuda_runtime.h>
#include <cuda_bf16.h>
#include <stdint.h>

#define FMAXV 3.4028235e38f

// ============================================================
// Device scratch (allocation-free). All split buffers: 2 bf16 planes
// (hi, residual), native layouts, no transposes.
// Reassociation: y = att^T @ (x @ (WV@Wout)) + u.
// Wcat packs [WK | WQ | W2] column-wise: [1024][3072] trans layout.
// KQU packs [K | Q | U] column-wise: [4096][3072].
// ============================================================
__device__ __nv_bfloat16 g_xS  [2ull*4096*1024];   // [n][m]
__device__ __nv_bfloat16 g_Wcat[2ull*1024*3072];   // [k][3n]: WK|WQ|W2
__device__ __nv_bfloat16 g_WVs [2ull*1024*1024];   // [m][d] (W2 gemm A)
__device__ __nv_bfloat16 g_Wos [2ull*1024*1024];   // [d][m] (W2 gemm B, trans)
__device__ __nv_bfloat16 g_KQU [2ull*4096*3072];   // [j][3k]: K|Q|U
__device__ __nv_bfloat16 g_attB[2ull*4096*4096];   // [r][a] (from softmax)
__device__ float         g_part[4096ull*1024];     // attV split-K partial
__device__ float         g_u   [1024];

// ============================================================
// Helpers (base sm_103-safe: mma.sync bf16, cp.async, ldmatrix)
// ============================================================
__device__ __forceinline__ uint32_t smem_u32(const void* p) {
    uint32_t a;
    asm("{ .reg .u64 t; cvta.to.shared.u64 t, %1; cvt.u32.u64 %0, t; }" : "=r"(a) : "l"(p));
    return a;
}
__device__ __forceinline__ void cp16(void* s, const void* g) {
    uint32_t a = smem_u32(s);
    asm volatile("cp.async.cg.shared.global [%0], [%1], 16;" :: "r"(a), "l"(g));
}
#define CP_COMMIT()  asm volatile("cp.async.commit_group;" ::: "memory")
#define CP_WAIT(N)   asm volatile("cp.async.wait_group %0;" :: "n"(N) : "memory")

__device__ __forceinline__ void ldsm4(uint32_t* r, uint32_t a) {
    asm volatile("ldmatrix.sync.aligned.m8n8.x4.shared.b16 {%0,%1,%2,%3}, [%4];"
        : "=r"(r[0]), "=r"(r[1]), "=r"(r[2]), "=r"(r[3]) : "r"(a));
}
__device__ __forceinline__ void ldsm4t(uint32_t* r, uint32_t a) {
    asm volatile("ldmatrix.sync.aligned.m8n8.x4.trans.shared.b16 {%0,%1,%2,%3}, [%4];"
        : "=r"(r[0]), "=r"(r[1]), "=r"(r[2]), "=r"(r[3]) : "r"(a));
}
__device__ __forceinline__ void ldsm2(uint32_t* r, uint32_t a) {
    asm volatile("ldmatrix.sync.aligned.m8n8.x2.shared.b16 {%0,%1}, [%2];"
        : "=r"(r[0]), "=r"(r[1]) : "r"(a));
}
__device__ __forceinline__ void ldsm2t(uint32_t* r, uint32_t a) {
    asm volatile("ldmatrix.sync.aligned.m8n8.x2.trans.shared.b16 {%0,%1}, [%2];"
        : "=r"(r[0]), "=r"(r[1]) : "r"(a));
}
__device__ __forceinline__ void mma16(float* c, const uint32_t* a, const uint32_t* b) {
    asm volatile(
        "mma.sync.aligned.m16n8k16.row.col.f32.bf16.bf16.f32 "
        "{%0,%1,%2,%3}, {%4,%5,%6,%7}, {%8,%9}, {%0,%1,%2,%3};"
        : "+f"(c[0]), "+f"(c[1]), "+f"(c[2]), "+f"(c[3])
        : "r"(a[0]), "r"(a[1]), "r"(a[2]), "r"(a[3]), "r"(b[0]), "r"(b[1]));
}
__device__ __forceinline__ uint32_t split2_u32(float v0, float v1, uint32_t* lo) {
    __nv_bfloat16 h0 = __float2bfloat16_rn(v0);
    __nv_bfloat16 h1 = __float2bfloat16_rn(v1);
    __nv_bfloat16 l0 = __float2bfloat16_rn(v0 - __bfloat162float(h0));
    __nv_bfloat16 l1 = __float2bfloat16_rn(v1 - __bfloat162float(h1));
    *lo = (uint32_t)__bfloat16_as_ushort(l0) | ((uint32_t)__bfloat16_as_ushort(l1) << 16);
    return (uint32_t)__bfloat16_as_ushort(h0) | ((uint32_t)__bfloat16_as_ushort(h1) << 16);
}

// ============================================================
// GEMM (R6 core schedule, BK/NS templated): D[m,n] = sum_k A[m,k]*B[n,k].
// A,B = 2-plane bf16 split; 3 products/K16 (Ah*Bh + Ah*Bm + Am*Bh).
// Tile 128x128, 256 thr (8 warps, 64x32), NS-stage cp.async,
// one barrier per BK-chunk, issue() at END of loop body (LDSMs first).
// EPI: 0 = bf16 split out; 1 = fp32 out;
//      3 = bf16 split out, alpha applied ONLY to JB-block 1 (fused Q scale)
// SKIP: 1 = fully-masked logits tile -> return, no writes
//       2 = attV: IB reversed (longest first), K-chunks j < IB-129,
//           blockIdx.z halves the chunk range; z=1 writes Cv2.
// ============================================================
template <int TRA, int TRB, int EPI, int SKIP, int BK, int NS>
__global__ void __launch_bounds__(256, 2)
gemm_bf16(const __nv_bfloat16* __restrict__ A, const __nv_bfloat16* __restrict__ B,
          void* __restrict__ Cv, int lda, int ldb, int ldc,
          long long planeA, long long planeB, long long planeC,
          int nch, float alpha, void* __restrict__ Cv2)
{
    constexpr int AROW = TRA ? 136 : (BK + 8);    // padded row strides (halves)
    constexpr int BROW = TRB ? 136 : (BK + 8);
    constexpr int APL  = TRA ? BK * 136 : 128 * (BK + 8);
    constexpr int BPL  = TRB ? BK * 136 : 128 * (BK + 8);
    constexpr int STG  = 2 * APL + 2 * BPL;       // Ah, Am, Bh, Bm (halves)
    constexpr int KSN  = BK / 16;                 // k16 sub-chunks per chunk

    const int tid = threadIdx.x;
    const int IBb = (SKIP == 2) ? (31 - blockIdx.y) : blockIdx.y;
    const int IB = IBb * 128;
    const int JB = blockIdx.x * 128;

    if (SKIP == 1 && (JB + 127 - IB) <= 256) return;

    extern __shared__ __nv_bfloat16 smh[];

    int t0 = 0, t1 = nch;
    if (SKIP == 2) {
        int n1 = IB - 129; if (n1 < 0) n1 = 0;
        int T = (n1 + BK - 1) / BK; if (T > nch) T = nch;
        int Th = (T + 1) >> 1;
        if (blockIdx.z == 0) { t1 = Th; }
        else                 { t0 = Th; t1 = T; Cv = Cv2; }
    }

    const int lane = tid & 31, w = tid >> 5;
    const int RW = (w >> 2) * 64, CW = (w & 3) * 32;

    // ldmatrix per-lane offsets (halves within plane)
    const int lq = lane >> 3, li = lane & 7, q2 = lq & 1;
    int aoff, boff;
    if (TRA) aoff = ((lq >> 1) * 8 + li) * AROW + RW + (lq & 1) * 8;
    else     aoff = (RW + (lq & 1) * 8 + li) * AROW + (lq >> 1) * 8;
    if (TRB) boff = (q2 * 8 + li) * BROW + CW;
    else     boff = (CW + li) * BROW + q2 * 8;
    constexpr int AMT = TRA ? 16 : 16 * AROW;     // per-mt advance
    constexpr int BNT = TRB ? 8 : 8 * BROW;       // per-nt advance
    constexpr int AKS = TRA ? 16 * 136 : 16;      // per-k16 advance
    constexpr int BKS = TRB ? 16 * 136 : 16;
    const uint32_t sb0 = smem_u32(smh);

    auto issue = [&](int t) {
        int k0 = t * BK;
        __nv_bfloat16* sb = smh + (t % NS) * STG;
        constexpr int APPL = TRA ? BK * 16 : 128 * (BK / 8);  // cp16 per A plane
        constexpr int AIT  = (2 * APPL) / 256;
        #pragma unroll
        for (int it = 0; it < AIT; it++) {
            int idx = tid + it * 256;
            int pl = idx / APPL, r = idx % APPL;
            __nv_bfloat16* dst; const __nv_bfloat16* src;
            if (TRA) { int row = r >> 4, ch = r & 15;
                dst = sb + pl * APL + row * AROW + ch * 8;
                src = A + (size_t)pl * planeA + (size_t)(k0 + row) * lda + IB + ch * 8;
            } else { int row = r / (BK / 8), ch = r % (BK / 8);
                dst = sb + pl * APL + row * AROW + ch * 8;
                src = A + (size_t)pl * planeA + (size_t)(IB + row) * lda + k0 + ch * 8;
            }
            cp16(dst, src);
        }
        constexpr int BPPL = TRB ? BK * 16 : 128 * (BK / 8);
        constexpr int BIT  = (2 * BPPL) / 256;
        #pragma unroll
        for (int it = 0; it < BIT; it++) {
            int idx = tid + it * 256;
            int pl = idx / BPPL, r = idx % BPPL;
            __nv_bfloat16* dst; const __nv_bfloat16* src;
            if (TRB) { int row = r >> 4, ch = r & 15;
                dst = sb + 2 * APL + pl * BPL + row * BROW + ch * 8;
                src = B + (size_t)pl * planeB + (size_t)(k0 + row) * ldb + JB + ch * 8;
            } else { int row = r / (BK / 8), ch = r % (BK / 8);
                dst = sb + 2 * APL + pl * BPL + row * BROW + ch * 8;
                src = B + (size_t)pl * planeB + (size_t)(JB + row) * ldb + k0 + ch * 8;
            }
            cp16(dst, src);
        }
        CP_COMMIT();
    };

    float acc[64];
    #pragma unroll
    for (int i = 0; i < 64; i++) acc[i] = 0.f;

    #pragma unroll
    for (int p = 0; p < NS - 1; p++)
        if (t0 + p < t1) issue(t0 + p);

    for (int t = t0; t < t1; t++) {
        if (NS == 4) {
            if (t + 2 < t1) { CP_WAIT(2); } else if (t + 1 < t1) { CP_WAIT(1); } else { CP_WAIT(0); }
        } else {
            if (t + 1 < t1) { CP_WAIT(1); } else { CP_WAIT(0); }
        }
        __syncthreads();

        uint32_t sbb = sb0 + (uint32_t)((t % NS) * STG) * 2;

        #pragma unroll
        for (int ks = 0; ks < KSN; ks++) {
            uint32_t aH = sbb + (uint32_t)(aoff + ks * AKS) * 2;
            uint32_t aM = aH + APL * 2;
            uint32_t bHa = sbb + (uint32_t)(2 * APL + boff + ks * BKS) * 2;
            uint32_t bMa = bHa + BPL * 2;

            uint32_t af[16], am[16], bh[8], bm[8];
            #pragma unroll
            for (int mt = 0; mt < 4; mt++) {
                if (TRA) ldsm4t(af + mt * 4, aH + mt * AMT * 2);
                else     ldsm4 (af + mt * 4, aH + mt * AMT * 2);
            }
            #pragma unroll
            for (int nt = 0; nt < 4; nt++) {
                if (TRB) ldsm2t(bh + nt * 2, bHa + nt * BNT * 2);
                else     ldsm2 (bh + nt * 2, bHa + nt * BNT * 2);
            }
            #pragma unroll
            for (int mt = 0; mt < 4; mt++)
                #pragma unroll
                for (int nt = 0; nt < 4; nt++)
                    mma16(&acc[(mt * 4 + nt) * 4], af + mt * 4, bh + nt * 2);
            #pragma unroll
            for (int nt = 0; nt < 4; nt++) {
                if (TRB) ldsm2t(bm + nt * 2, bMa + nt * BNT * 2);
                else     ldsm2 (bm + nt * 2, bMa + nt * BNT * 2);
            }
            #pragma unroll
            for (int mt = 0; mt < 4; mt++)
                #pragma unroll
                for (int nt = 0; nt < 4; nt++)
                    mma16(&acc[(mt * 4 + nt) * 4], af + mt * 4, bm + nt * 2);
            #pragma unroll
            for (int mt = 0; mt < 4; mt++) {
                if (TRA) ldsm4t(am + mt * 4, aM + mt * AMT * 2);
                else     ldsm4 (am + mt * 4, aM + mt * AMT * 2);
            }
            #pragma unroll
            for (int mt = 0; mt < 4; mt++)
                #pragma unroll
                for (int nt = 0; nt < 4; nt++)
                    mma16(&acc[(mt * 4 + nt) * 4], am + mt * 4, bh + nt * 2);
        }

        if (t + NS - 1 < t1) issue(t + NS - 1);   // writes stage (t-1)%NS, freed by top barrier
    }

    // ---------------- epilogue ----------------
    const float al = (EPI == 3) ? (((JB >> 10) == 1) ? alpha : 1.0f) : alpha;
    const int eg = lane >> 2, etg = lane & 3;
    #pragma unroll
    for (int mt = 0; mt < 4; mt++) {
        #pragma unroll
        for (int nt = 0; nt < 4; nt++) {
            const float* cc = &acc[(mt * 4 + nt) * 4];
            int r0 = IB + RW + mt * 16 + eg;
            int c0 = JB + CW + nt * 8 + 2 * etg;
            #pragma unroll
            for (int half = 0; half < 2; half++) {
                int r = r0 + half * 8;
                float v0 = cc[half * 2 + 0] * al;
                float v1 = cc[half * 2 + 1] * al;
                if (EPI == 1) {
                    *(float2*)((float*)Cv + (size_t)r * ldc + c0) = make_float2(v0, v1);
                } else {
                    __nv_bfloat16* dst = (__nv_bfloat16*)Cv + (size_t)r * ldc + c0;
                    uint32_t lo;
                    uint32_t hi = split2_u32(v0, v1, &lo);
                    *(uint32_t*)dst            = hi;
                    *(uint32_t*)(dst + planeC) = lo;
                }
            }
        }
    }
}

// ============================================================
// Elementwise split to 2 bf16 planes (float4 vectorized)
// ============================================================
__global__ void __launch_bounds__(256)
split_kernel(const float* __restrict__ in, __nv_bfloat16* __restrict__ out, size_t S)
{
    size_t S4 = S >> 2;
    uint32_t* oh = (uint32_t*)out;
    uint32_t* ol = (uint32_t*)(out + S);
    for (size_t i4 = (size_t)blockIdx.x * blockDim.x + threadIdx.x; i4 < S4;
         i4 += (size_t)gridDim.x * blockDim.x) {
        float4 v = ((const float4*)in)[i4];
        uint32_t l0, l1;
        uint32_t h0 = split2_u32(v.x, v.y, &l0);
        uint32_t h1 = split2_u32(v.z, v.w, &l1);
        oh[i4 * 2] = h0; oh[i4 * 2 + 1] = h1;
        ol[i4 * 2] = l0; ol[i4 * 2 + 1] = l1;
    }
}

// Fused weight split: y=0 -> WK into Wcat cols [0,1024); y=1 -> WQ into
// Wcat cols [1024,2048); y=2 -> WV dense; y=3 -> Wout dense.
__global__ void __launch_bounds__(256)
splitW_kernel(const float* __restrict__ w0, const float* __restrict__ w1,
              const float* __restrict__ w2, const float* __restrict__ w3,
              __nv_bfloat16* __restrict__ wcat,
              __nv_bfloat16* __restrict__ ov, __nv_bfloat16* __restrict__ oo)
{
    const size_t S = 1024ull * 1024;
    const size_t PCAT = 1024ull * 3072;
    size_t S4 = S >> 2;
    const int which = blockIdx.y;
    const float* in = (which == 0) ? w0 : (which == 1) ? w1 : (which == 2) ? w2 : w3;

    for (size_t i4 = (size_t)blockIdx.x * blockDim.x + threadIdx.x; i4 < S4;
         i4 += (size_t)gridDim.x * blockDim.x) {
        float4 v = ((const float4*)in)[i4];
        uint32_t l0, l1;
        uint32_t h0 = split2_u32(v.x, v.y, &l0);
        uint32_t h1 = split2_u32(v.z, v.w, &l1);
        if (which < 2) {
            size_t e = i4 * 4;
            size_t row = e >> 10, col = e & 1023;
            size_t o = row * 3072 + which * 1024 + col;   // halves, 4-aligned
            uint2* dh = (uint2*)(wcat + o);
            uint2* dl = (uint2*)(wcat + PCAT + o);
            *dh = make_uint2(h0, h1);
            *dl = make_uint2(l0, l1);
        } else {
            __nv_bfloat16* out = (which == 2) ? ov : oo;
            uint32_t* oh = (uint32_t*)out;
            uint32_t* ol = (uint32_t*)(out + S);
            oh[i4 * 2] = h0; oh[i4 * 2 + 1] = h1;
            ol[i4 * 2] = l0; ol[i4 * 2 + 1] = l1;
        }
    }
}

// ============================================================
// rank-1 uniform-row correction from U planes (inside KQU):
// u[k] = (1/4096) * sum_{j>=3839} (Uh+Ul)[j][k]
// ============================================================
__global__ void __launch_bounds__(1024)
rank1_kernel(const __nv_bfloat16* __restrict__ Up, float* __restrict__ u,
             int ld, long long plane)
{
    __shared__ float part[8][128];
    const int kl = threadIdx.x & 127;
    const int js = threadIdx.x >> 7;          // 0..7
    const int k = blockIdx.x * 128 + kl;
    float s = 0.f;
    for (int j = 3839 + js; j < 4096; j += 8) {
        size_t o = (size_t)j * ld + k;
        s += __bfloat162float(Up[o]) + __bfloat162float(Up[plane + o]);
    }
    part[js][kl] = s;
    __syncthreads();
    if (threadIdx.x < 128) {
        float t = 0.f;
        #pragma unroll
        for (int q = 0; q < 8; q++) t += part[q][threadIdx.x];
        u[k] = t * (1.0f / 4096.0f);
    }
}

// ============================================================
// Combine: y[i][k] = part0(y in-place) + part1 + u[k]
// ============================================================
__global__ void __launch_bounds__(256)
combine_kernel(float* __restrict__ y, const float* __restrict__ part,
               const float* __restrict__ u)
{
    const size_t S4 = (4096ull * 1024) >> 2;
    for (size_t i4 = (size_t)blockIdx.x * blockDim.x + threadIdx.x; i4 < S4;
         i4 += (size_t)gridDim.x * blockDim.x) {
        float4 a = ((float4*)y)[i4];
        float4 b = ((const float4*)part)[i4];
        float4 uu = ((const float4*)u)[i4 & 255];   // k = (i4*4) % 1024
        a.x += b.x + uu.x; a.y += b.y + uu.y;
        a.z += b.z + uu.z; a.w += b.w + uu.w;
        ((float4*)y)[i4] = a;
    }
}

// ============================================================
// Structured softmax + fused bf16 split, one block per row.
// ============================================================
__global__ void __launch_bounds__(256)
softmax_split(float* __restrict__ att, __nv_bfloat16* __restrict__ ab, long long PA)
{
    const int i = blockIdx.x;
    const int tid = threadIdx.x;
    float* p = att + (size_t)i * 4096;
    __nv_bfloat16* bhp = ab + (size_t)i * 4096;
    __nv_bfloat16* blp = bhp + PA;

    if (i >= 3839) {
        const float c = 1.0f / 4096.0f;
        float4 cv = make_float4(c, c, c, c);
        #pragma unroll
        for (int q = 0; q < 4; q++) ((float4*)p)[tid + q * 256] = cv;
        uint4 z = make_uint4(0, 0, 0, 0);
        #pragma unroll
        for (int q = 0; q < 2; q++) {
            ((uint4*)bhp)[tid + q * 256] = z;
            ((uint4*)blp)[tid + q * 256] = z;
        }
        return;
    }

    const int start = i + 257;
    const int s16 = start & ~15;
    const int nv4 = (4096 - s16) >> 2;
    float4* live = (float4*)(p + s16);

    float4 v[4];
    float mx = -FMAXV;
    #pragma unroll
    for (int q = 0; q < 4; q++) {
        int i4 = tid + q * 256;
        if (i4 < nv4) {
            float4 tv = live[i4];
            int j0 = s16 + i4 * 4;
            if (j0 < start) {
                if (j0 + 0 < start) tv.x = -FMAXV;
                if (j0 + 1 < start) tv.y = -FMAXV;
                if (j0 + 2 < start) tv.z = -FMAXV;
                if (j0 + 3 < start) tv.w = -FMAXV;
            }
            v[q] = tv;
            mx = fmaxf(mx, fmaxf(fmaxf(tv.x, tv.y), fmaxf(tv.z, tv.w)));
        }
    }
    #pragma unroll
    for (int o = 16; o > 0; o >>= 1) mx = fmaxf(mx, __shfl_xor_sync(0xffffffffu, mx, o));
    __shared__ float red[8];
    if ((tid & 31) == 0) red[tid >> 5] = mx;
    __syncthreads();
    mx = red[0];
    #pragma unroll
    for (int ww = 1; ww < 8; ww++) mx = fmaxf(mx, red[ww]);
    __syncthreads();

    float s = 0.f;
    #pragma unroll
    for (int q = 0; q < 4; q++) {
        if (tid + q * 256 < nv4) {
            v[q].x = expf(v[q].x - mx); s += v[q].x;
            v[q].y = expf(v[q].y - mx); s += v[q].y;
            v[q].z = expf(v[q].z - mx); s += v[q].z;
            v[q].w = expf(v[q].w - mx); s += v[q].w;
        }
    }
    #pragma unroll
    for (int o = 16; o > 0; o >>= 1) s += __shfl_xor_sync(0xffffffffu, s, o);
    if ((tid & 31) == 0) red[tid >> 5] = s;
    __syncthreads();
    s = red[0];
    #pragma unroll
    for (int ww = 1; ww < 8; ww++) s += red[ww];

    float inv = 1.0f / s;
    uint2* bhl = (uint2*)(bhp + s16);
    uint2* bll = (uint2*)(blp + s16);
    #pragma unroll
    for (int q = 0; q < 4; q++) {
        int i4 = tid + q * 256;
        if (i4 < nv4) {
            v[q].x *= inv; v[q].y *= inv; v[q].z *= inv; v[q].w *= inv;
            live[i4] = v[q];
            uint32_t l0, l1;
            uint32_t h0 = split2_u32(v[q].x, v[q].y, &l0);
            uint32_t h1 = split2_u32(v[q].z, v[q].w, &l1);
            bhl[i4] = make_uint2(h0, h1);
            bll[i4] = make_uint2(l0, l1);
        }
    }
    // zero heads
    float4 z4 = make_float4(0.f, 0.f, 0.f, 0.f);
    int nz4 = s16 >> 2;
    for (int i4 = tid; i4 < nz4; i4 += 256) ((float4*)p)[i4] = z4;
    uint2 z2 = make_uint2(0, 0);
    for (int i2 = tid; i2 < nz4; i2 += 256) {
        ((uint2*)bhp)[i2] = z2;
        ((uint2*)blp)[i2] = z2;
    }
}

// ============================================================
// Host
// ============================================================
extern "C" void kernel_launch(void* const* d_in, const int* in_sizes, int n_in,
                              void* d_out, int out_size)
{
    const float* x    = (const float*)d_in[0];
    const float* WK   = (const float*)d_in[1];
    const float* WQ   = (const float*)d_in[2];
    const float* WV   = (const float*)d_in[3];
    const float* Wout = (const float*)d_in[4];

    const int m = 1024;
    const int n = in_sizes[0] / m;   // 4096

    float* y_out = (float*)d_out;                 // [n, m]
    float* att   = y_out + (size_t)n * m;         // [n, n]

    __nv_bfloat16 *pxS, *pWcat, *pWV, *pWo, *pKQU, *pattB;
    float *pu, *ppart;
    cudaGetSymbolAddress((void**)&pxS,   g_xS);
    cudaGetSymbolAddress((void**)&pWcat, g_Wcat);
    cudaGetSymbolAddress((void**)&pWV,   g_WVs);
    cudaGetSymbolAddress((void**)&pWo,   g_Wos);
    cudaGetSymbolAddress((void**)&pKQU,  g_KQU);
    cudaGetSymbolAddress((void**)&pattB, g_attB);
    cudaGetSymbolAddress((void**)&ppart, g_part);
    cudaGetSymbolAddress((void**)&pu,    g_u);

    // dynamic smem per instantiation
    const int SM01 = 3 * (2 * (128 * 40) + 2 * (32 * 136)) * 2;  // BK32/NS3: 113664
    const int SM00 = 4 * (4 * (128 * 24)) * 2;                   // BK16/NS4: 98304
    const int SM11 = 3 * (4 * (32 * 136)) * 2;                   // BK32/NS3: 104448

    cudaFuncSetAttribute(gemm_bf16<0, 1, 0, 0, 32, 3>, cudaFuncAttributeMaxDynamicSharedMemorySize, SM01);
    cudaFuncSetAttribute(gemm_bf16<0, 1, 3, 0, 32, 3>, cudaFuncAttributeMaxDynamicSharedMemorySize, SM01);
    cudaFuncSetAttribute(gemm_bf16<0, 0, 1, 1, 16, 4>, cudaFuncAttributeMaxDynamicSharedMemorySize, SM00);
    cudaFuncSetAttribute(gemm_bf16<1, 1, 1, 2, 32, 3>, cudaFuncAttributeMaxDynamicSharedMemorySize, SM11);

    const long long PX   = 4096LL * 1024;   // xS plane
    const long long PW   = 1024LL * 1024;   // dense weight plane
    const long long PCAT = 1024LL * 3072;   // Wcat plane
    const long long PKQ  = 4096LL * 3072;   // KQU plane
    const long long PA   = 4096LL * 4096;   // attB plane

    // Elementwise splits only — NO transposes.
    split_kernel<<<2048, 256>>>(x, pxS, (size_t)n * m);
    splitW_kernel<<<dim3(512, 4), 256>>>(WK, WQ, WV, Wout, pWcat, pWV, pWo);

    // W2 = WV@Wout -> bf16 split into Wcat cols [2048,3072)
    gemm_bf16<0, 1, 0, 0, 32, 3><<<dim3(8, 8), 256, SM01>>>(
        pWV, pWo, pWcat + 2048, 1024, 1024, 3072, PW, PW, PCAT, 32, 1.0f, nullptr);

    // Fused K|Q|U = x @ Wcat  (Q block scaled by 0.06 in epilogue) -> KQU split
    gemm_bf16<0, 1, 3, 0, 32, 3><<<dim3(24, 32), 256, SM01>>>(
        pxS, pWcat, pKQU, 1024, 3072, 3072, PX, PCAT, PKQ, 32, 0.06f, nullptr);

    // logits = Q@K^T (A = KQU+1024, B = KQU+0, both ld 3072) -> fp32 att
    gemm_bf16<0, 0, 1, 1, 16, 4><<<dim3(32, 32), 256, SM00>>>(
        pKQU + 1024, pKQU, att, 3072, 3072, 4096, PKQ, PKQ, 0, 64, 1.0f, nullptr);

    // softmax + fused bf16 split (row-major planes)
    softmax_split<<<n, 256>>>(att, pattB, PA);

    // rank-1 uniform-row vector from U planes (inside KQU)
    rank1_kernel<<<8, 1024>>>(pKQU + 2048, pu, 3072, PKQ);

    // y_partial = att^T @ U  (split-K x2, longest-first; z=0 -> y_out, z=1 -> part)
    gemm_bf16<1, 1, 1, 2, 32, 3><<<dim3(8, 32, 2), 256, SM11>>>(
        pattB, pKQU + 2048, y_out, 4096, 3072, 1024, PA, PKQ, 0, 128, 1.0f, ppart);

    // y = y + part + u
    combine_kernel<<<2048, 256>>>(y_out, ppart, pu);
}

// round 15
// speedup vs baseline: 1.3974x; 1.0040x over previous
#include <cuda_runtime.h>
#include <cuda_bf16.h>
#include <stdint.h>

#define FMAXV 3.4028235e38f

// ============================================================
// Device scratch (allocation-free). All split buffers: 2 bf16 planes
// (hi, residual), native layouts, no transposes.
// Reassociation: y = att^T @ (x @ (WV@Wout)) + u.
// Wcat packs [WK | WQ | W2] column-wise: [1024][3072] trans layout.
// KQU packs [K | Q | U] column-wise: [4096][3072].
// ============================================================
__device__ __nv_bfloat16 g_xS  [2ull*4096*1024];   // [n][m]
__device__ __nv_bfloat16 g_Wcat[2ull*1024*3072];   // [k][3n]: WK|WQ|W2
__device__ __nv_bfloat16 g_WVs [2ull*1024*1024];   // [m][d] (W2 gemm A)
__device__ __nv_bfloat16 g_Wos [2ull*1024*1024];   // [d][m] (W2 gemm B, trans)
__device__ __nv_bfloat16 g_KQU [2ull*4096*3072];   // [j][3k]: K|Q|U
__device__ __nv_bfloat16 g_attB[2ull*4096*4096];   // [r][a] (from softmax)
__device__ float         g_part[4096ull*1024];     // attV split-K partial
__device__ float         g_u   [1024];

// ============================================================
// Helpers (base sm_103-safe: mma.sync bf16, cp.async, ldmatrix)
// ============================================================
__device__ __forceinline__ uint32_t smem_u32(const void* p) {
    uint32_t a;
    asm("{ .reg .u64 t; cvta.to.shared.u64 t, %1; cvt.u32.u64 %0, t; }" : "=r"(a) : "l"(p));
    return a;
}
__device__ __forceinline__ void cp16(void* s, const void* g) {
    uint32_t a = smem_u32(s);
    asm volatile("cp.async.cg.shared.global [%0], [%1], 16;" :: "r"(a), "l"(g));
}
#define CP_COMMIT()  asm volatile("cp.async.commit_group;" ::: "memory")
#define CP_WAIT(N)   asm volatile("cp.async.wait_group %0;" :: "n"(N) : "memory")

__device__ __forceinline__ void ldsm4(uint32_t* r, uint32_t a) {
    asm volatile("ldmatrix.sync.aligned.m8n8.x4.shared.b16 {%0,%1,%2,%3}, [%4];"
        : "=r"(r[0]), "=r"(r[1]), "=r"(r[2]), "=r"(r[3]) : "r"(a));
}
__device__ __forceinline__ void ldsm4t(uint32_t* r, uint32_t a) {
    asm volatile("ldmatrix.sync.aligned.m8n8.x4.trans.shared.b16 {%0,%1,%2,%3}, [%4];"
        : "=r"(r[0]), "=r"(r[1]), "=r"(r[2]), "=r"(r[3]) : "r"(a));
}
__device__ __forceinline__ void ldsm2(uint32_t* r, uint32_t a) {
    asm volatile("ldmatrix.sync.aligned.m8n8.x2.shared.b16 {%0,%1}, [%2];"
        : "=r"(r[0]), "=r"(r[1]) : "r"(a));
}
__device__ __forceinline__ void ldsm2t(uint32_t* r, uint32_t a) {
    asm volatile("ldmatrix.sync.aligned.m8n8.x2.trans.shared.b16 {%0,%1}, [%2];"
        : "=r"(r[0]), "=r"(r[1]) : "r"(a));
}
__device__ __forceinline__ void mma16(float* c, const uint32_t* a, const uint32_t* b) {
    asm volatile(
        "mma.sync.aligned.m16n8k16.row.col.f32.bf16.bf16.f32 "
        "{%0,%1,%2,%3}, {%4,%5,%6,%7}, {%8,%9}, {%0,%1,%2,%3};"
        : "+f"(c[0]), "+f"(c[1]), "+f"(c[2]), "+f"(c[3])
        : "r"(a[0]), "r"(a[1]), "r"(a[2]), "r"(a[3]), "r"(b[0]), "r"(b[1]));
}
__device__ __forceinline__ uint32_t split2_u32(float v0, float v1, uint32_t* lo) {
    __nv_bfloat16 h0 = __float2bfloat16_rn(v0);
    __nv_bfloat16 h1 = __float2bfloat16_rn(v1);
    __nv_bfloat16 l0 = __float2bfloat16_rn(v0 - __bfloat162float(h0));
    __nv_bfloat16 l1 = __float2bfloat16_rn(v1 - __bfloat162float(h1));
    *lo = (uint32_t)__bfloat16_as_ushort(l0) | ((uint32_t)__bfloat16_as_ushort(l1) << 16);
    return (uint32_t)__bfloat16_as_ushort(h0) | ((uint32_t)__bfloat16_as_ushort(h1) << 16);
}

// ============================================================
// GEMM (R6 core schedule; ks-body reordered so every LDSM after the
// first group is covered by a 16-MMA burst):
//   LDSM af, am, bh -> MMA hh (bm loads under it) -> MMA hm -> MMA mh
// D[m,n] = sum_k A[m,k]*B[n,k]; A,B = 2-plane bf16 split.
// Tile 128x128, 256 thr (8 warps, 64x32), NS-stage cp.async,
// one barrier per BK-chunk, issue() at END of loop body.
// EPI: 0 = bf16 split out; 1 = fp32 out;
//      3 = bf16 split out, alpha applied ONLY to JB-block 1 (fused Q scale)
// SKIP: 1 = fully-masked logits tile -> return, no writes
//       2 = attV: IB reversed (longest first), K-chunks j < IB-129,
//           blockIdx.z halves the chunk range; z=1 writes Cv2.
// ============================================================
template <int TRA, int TRB, int EPI, int SKIP, int BK, int NS>
__global__ void __launch_bounds__(256, 2)
gemm_bf16(const __nv_bfloat16* __restrict__ A, const __nv_bfloat16* __restrict__ B,
          void* __restrict__ Cv, int lda, int ldb, int ldc,
          long long planeA, long long planeB, long long planeC,
          int nch, float alpha, void* __restrict__ Cv2)
{
    constexpr int AROW = TRA ? 136 : (BK + 8);    // padded row strides (halves)
    constexpr int BROW = TRB ? 136 : (BK + 8);
    constexpr int APL  = TRA ? BK * 136 : 128 * (BK + 8);
    constexpr int BPL  = TRB ? BK * 136 : 128 * (BK + 8);
    constexpr int STG  = 2 * APL + 2 * BPL;       // Ah, Am, Bh, Bm (halves)
    constexpr int KSN  = BK / 16;                 // k16 sub-chunks per chunk

    const int tid = threadIdx.x;
    const int IBb = (SKIP == 2) ? (31 - blockIdx.y) : blockIdx.y;
    const int IB = IBb * 128;
    const int JB = blockIdx.x * 128;

    if (SKIP == 1 && (JB + 127 - IB) <= 256) return;

    extern __shared__ __nv_bfloat16 smh[];

    int t0 = 0, t1 = nch;
    if (SKIP == 2) {
        int n1 = IB - 129; if (n1 < 0) n1 = 0;
        int T = (n1 + BK - 1) / BK; if (T > nch) T = nch;
        int Th = (T + 1) >> 1;
        if (blockIdx.z == 0) { t1 = Th; }
        else                 { t0 = Th; t1 = T; Cv = Cv2; }
    }

    const int lane = tid & 31, w = tid >> 5;
    const int RW = (w >> 2) * 64, CW = (w & 3) * 32;

    // ldmatrix per-lane offsets (halves within plane)
    const int lq = lane >> 3, li = lane & 7, q2 = lq & 1;
    int aoff, boff;
    if (TRA) aoff = ((lq >> 1) * 8 + li) * AROW + RW + (lq & 1) * 8;
    else     aoff = (RW + (lq & 1) * 8 + li) * AROW + (lq >> 1) * 8;
    if (TRB) boff = (q2 * 8 + li) * BROW + CW;
    else     boff = (CW + li) * BROW + q2 * 8;
    constexpr int AMT = TRA ? 16 : 16 * AROW;     // per-mt advance
    constexpr int BNT = TRB ? 8 : 8 * BROW;       // per-nt advance
    constexpr int AKS = TRA ? 16 * 136 : 16;      // per-k16 advance
    constexpr int BKS = TRB ? 16 * 136 : 16;
    const uint32_t sb0 = smem_u32(smh);

    auto issue = [&](int t) {
        int k0 = t * BK;
        __nv_bfloat16* sb = smh + (t % NS) * STG;
        constexpr int APPL = TRA ? BK * 16 : 128 * (BK / 8);  // cp16 per A plane
        constexpr int AIT  = (2 * APPL) / 256;
        #pragma unroll
        for (int it = 0; it < AIT; it++) {
            int idx = tid + it * 256;
            int pl = idx / APPL, r = idx % APPL;
            __nv_bfloat16* dst; const __nv_bfloat16* src;
            if (TRA) { int row = r >> 4, ch = r & 15;
                dst = sb + pl * APL + row * AROW + ch * 8;
                src = A + (size_t)pl * planeA + (size_t)(k0 + row) * lda + IB + ch * 8;
            } else { int row = r / (BK / 8), ch = r % (BK / 8);
                dst = sb + pl * APL + row * AROW + ch * 8;
                src = A + (size_t)pl * planeA + (size_t)(IB + row) * lda + k0 + ch * 8;
            }
            cp16(dst, src);
        }
        constexpr int BPPL = TRB ? BK * 16 : 128 * (BK / 8);
        constexpr int BIT  = (2 * BPPL) / 256;
        #pragma unroll
        for (int it = 0; it < BIT; it++) {
            int idx = tid + it * 256;
            int pl = idx / BPPL, r = idx % BPPL;
            __nv_bfloat16* dst; const __nv_bfloat16* src;
            if (TRB) { int row = r >> 4, ch = r & 15;
                dst = sb + 2 * APL + pl * BPL + row * BROW + ch * 8;
                src = B + (size_t)pl * planeB + (size_t)(k0 + row) * ldb + JB + ch * 8;
            } else { int row = r / (BK / 8), ch = r % (BK / 8);
                dst = sb + 2 * APL + pl * BPL + row * BROW + ch * 8;
                src = B + (size_t)pl * planeB + (size_t)(JB + row) * ldb + k0 + ch * 8;
            }
            cp16(dst, src);
        }
        CP_COMMIT();
    };

    float acc[64];
    #pragma unroll
    for (int i = 0; i < 64; i++) acc[i] = 0.f;

    #pragma unroll
    for (int p = 0; p < NS - 1; p++)
        if (t0 + p < t1) issue(t0 + p);

    for (int t = t0; t < t1; t++) {
        if (NS == 4) {
            if (t + 2 < t1) { CP_WAIT(2); } else if (t + 1 < t1) { CP_WAIT(1); } else { CP_WAIT(0); }
        } else {
            if (t + 1 < t1) { CP_WAIT(1); } else { CP_WAIT(0); }
        }
        __syncthreads();

        uint32_t sbb = sb0 + (uint32_t)((t % NS) * STG) * 2;

        #pragma unroll
        for (int ks = 0; ks < KSN; ks++) {
            uint32_t aH = sbb + (uint32_t)(aoff + ks * AKS) * 2;
            uint32_t aM = aH + APL * 2;
            uint32_t bHa = sbb + (uint32_t)(2 * APL + boff + ks * BKS) * 2;
            uint32_t bMa = bHa + BPL * 2;

            uint32_t af[16], am[16], bh[8], bm[8];
            // front-load A hi+mid and B hi: every later LDSM hides under MMAs
            #pragma unroll
            for (int mt = 0; mt < 4; mt++) {
                if (TRA) ldsm4t(af + mt * 4, aH + mt * AMT * 2);
                else     ldsm4 (af + mt * 4, aH + mt * AMT * 2);
            }
            #pragma unroll
            for (int mt = 0; mt < 4; mt++) {
                if (TRA) ldsm4t(am + mt * 4, aM + mt * AMT * 2);
                else     ldsm4 (am + mt * 4, aM + mt * AMT * 2);
            }
            #pragma unroll
            for (int nt = 0; nt < 4; nt++) {
                if (TRB) ldsm2t(bh + nt * 2, bHa + nt * BNT * 2);
                else     ldsm2 (bh + nt * 2, bHa + nt * BNT * 2);
            }
            // pass 1: Ah*Bh; bm loads issued under this burst
            #pragma unroll
            for (int nt = 0; nt < 4; nt++) {
                if (TRB) ldsm2t(bm + nt * 2, bMa + nt * BNT * 2);
                else     ldsm2 (bm + nt * 2, bMa + nt * BNT * 2);
            }
            #pragma unroll
            for (int mt = 0; mt < 4; mt++)
                #pragma unroll
                for (int nt = 0; nt < 4; nt++)
                    mma16(&acc[(mt * 4 + nt) * 4], af + mt * 4, bh + nt * 2);
            // pass 2: Ah*Bm
            #pragma unroll
            for (int mt = 0; mt < 4; mt++)
                #pragma unroll
                for (int nt = 0; nt < 4; nt++)
                    mma16(&acc[(mt * 4 + nt) * 4], af + mt * 4, bm + nt * 2);
            // pass 3: Am*Bh
            #pragma unroll
            for (int mt = 0; mt < 4; mt++)
                #pragma unroll
                for (int nt = 0; nt < 4; nt++)
                    mma16(&acc[(mt * 4 + nt) * 4], am + mt * 4, bh + nt * 2);
        }

        if (t + NS - 1 < t1) issue(t + NS - 1);   // writes stage (t-1)%NS, freed by top barrier
    }

    // ---------------- epilogue ----------------
    const float al = (EPI == 3) ? (((JB >> 10) == 1) ? alpha : 1.0f) : alpha;
    const int eg = lane >> 2, etg = lane & 3;
    #pragma unroll
    for (int mt = 0; mt < 4; mt++) {
        #pragma unroll
        for (int nt = 0; nt < 4; nt++) {
            const float* cc = &acc[(mt * 4 + nt) * 4];
            int r0 = IB + RW + mt * 16 + eg;
            int c0 = JB + CW + nt * 8 + 2 * etg;
            #pragma unroll
            for (int half = 0; half < 2; half++) {
                int r = r0 + half * 8;
                float v0 = cc[half * 2 + 0] * al;
                float v1 = cc[half * 2 + 1] * al;
                if (EPI == 1) {
                    *(float2*)((float*)Cv + (size_t)r * ldc + c0) = make_float2(v0, v1);
                } else {
                    __nv_bfloat16* dst = (__nv_bfloat16*)Cv + (size_t)r * ldc + c0;
                    uint32_t lo;
                    uint32_t hi = split2_u32(v0, v1, &lo);
                    *(uint32_t*)dst            = hi;
                    *(uint32_t*)(dst + planeC) = lo;
                }
            }
        }
    }
}

// ============================================================
// Elementwise split to 2 bf16 planes (float4 vectorized)
// ============================================================
__global__ void __launch_bounds__(256)
split_kernel(const float* __restrict__ in, __nv_bfloat16* __restrict__ out, size_t S)
{
    size_t S4 = S >> 2;
    uint32_t* oh = (uint32_t*)out;
    uint32_t* ol = (uint32_t*)(out + S);
    for (size_t i4 = (size_t)blockIdx.x * blockDim.x + threadIdx.x; i4 < S4;
         i4 += (size_t)gridDim.x * blockDim.x) {
        float4 v = ((const float4*)in)[i4];
        uint32_t l0, l1;
        uint32_t h0 = split2_u32(v.x, v.y, &l0);
        uint32_t h1 = split2_u32(v.z, v.w, &l1);
        oh[i4 * 2] = h0; oh[i4 * 2 + 1] = h1;
        ol[i4 * 2] = l0; ol[i4 * 2 + 1] = l1;
    }
}

// Fused weight split: y=0 -> WK into Wcat cols [0,1024); y=1 -> WQ into
// Wcat cols [1024,2048); y=2 -> WV dense; y=3 -> Wout dense.
__global__ void __launch_bounds__(256)
splitW_kernel(const float* __restrict__ w0, const float* __restrict__ w1,
              const float* __restrict__ w2, const float* __restrict__ w3,
              __nv_bfloat16* __restrict__ wcat,
              __nv_bfloat16* __restrict__ ov, __nv_bfloat16* __restrict__ oo)
{
    const size_t S = 1024ull * 1024;
    const size_t PCAT = 1024ull * 3072;
    size_t S4 = S >> 2;
    const int which = blockIdx.y;
    const float* in = (which == 0) ? w0 : (which == 1) ? w1 : (which == 2) ? w2 : w3;

    for (size_t i4 = (size_t)blockIdx.x * blockDim.x + threadIdx.x; i4 < S4;
         i4 += (size_t)gridDim.x * blockDim.x) {
        float4 v = ((const float4*)in)[i4];
        uint32_t l0, l1;
        uint32_t h0 = split2_u32(v.x, v.y, &l0);
        uint32_t h1 = split2_u32(v.z, v.w, &l1);
        if (which < 2) {
            size_t e = i4 * 4;
            size_t row = e >> 10, col = e & 1023;
            size_t o = row * 3072 + which * 1024 + col;   // halves, 4-aligned
            uint2* dh = (uint2*)(wcat + o);
            uint2* dl = (uint2*)(wcat + PCAT + o);
            *dh = make_uint2(h0, h1);
            *dl = make_uint2(l0, l1);
        } else {
            __nv_bfloat16* out = (which == 2) ? ov : oo;
            uint32_t* oh = (uint32_t*)out;
            uint32_t* ol = (uint32_t*)(out + S);
            oh[i4 * 2] = h0; oh[i4 * 2 + 1] = h1;
            ol[i4 * 2] = l0; ol[i4 * 2 + 1] = l1;
        }
    }
}

// ============================================================
// rank-1 uniform-row correction from U planes (inside KQU):
// u[k] = (1/4096) * sum_{j>=3839} (Uh+Ul)[j][k]
// ============================================================
__global__ void __launch_bounds__(1024)
rank1_kernel(const __nv_bfloat16* __restrict__ Up, float* __restrict__ u,
             int ld, long long plane)
{
    __shared__ float part[8][128];
    const int kl = threadIdx.x & 127;
    const int js = threadIdx.x >> 7;          // 0..7
    const int k = blockIdx.x * 128 + kl;
    float s = 0.f;
    for (int j = 3839 + js; j < 4096; j += 8) {
        size_t o = (size_t)j * ld + k;
        s += __bfloat162float(Up[o]) + __bfloat162float(Up[plane + o]);
    }
    part[js][kl] = s;
    __syncthreads();
    if (threadIdx.x < 128) {
        float t = 0.f;
        #pragma unroll
        for (int q = 0; q < 8; q++) t += part[q][threadIdx.x];
        u[k] = t * (1.0f / 4096.0f);
    }
}

// ============================================================
// Combine: y[i][k] = part0(y in-place) + part1 + u[k]
// ============================================================
__global__ void __launch_bounds__(256)
combine_kernel(float* __restrict__ y, const float* __restrict__ part,
               const float* __restrict__ u)
{
    const size_t S4 = (4096ull * 1024) >> 2;
    for (size_t i4 = (size_t)blockIdx.x * blockDim.x + threadIdx.x; i4 < S4;
         i4 += (size_t)gridDim.x * blockDim.x) {
        float4 a = ((float4*)y)[i4];
        float4 b = ((const float4*)part)[i4];
        float4 uu = ((const float4*)u)[i4 & 255];   // k = (i4*4) % 1024
        a.x += b.x + uu.x; a.y += b.y + uu.y;
        a.z += b.z + uu.z; a.w += b.w + uu.w;
        ((float4*)y)[i4] = a;
    }
}

// ============================================================
// Structured softmax + fused bf16 split, one block per row.
// ============================================================
__global__ void __launch_bounds__(256)
softmax_split(float* __restrict__ att, __nv_bfloat16* __restrict__ ab, long long PA)
{
    const int i = blockIdx.x;
    const int tid = threadIdx.x;
    float* p = att + (size_t)i * 4096;
    __nv_bfloat16* bhp = ab + (size_t)i * 4096;
    __nv_bfloat16* blp = bhp + PA;

    if (i >= 3839) {
        const float c = 1.0f / 4096.0f;
        float4 cv = make_float4(c, c, c, c);
        #pragma unroll
        for (int q = 0; q < 4; q++) ((float4*)p)[tid + q * 256] = cv;
        uint4 z = make_uint4(0, 0, 0, 0);
        #pragma unroll
        for (int q = 0; q < 2; q++) {
            ((uint4*)bhp)[tid + q * 256] = z;
            ((uint4*)blp)[tid + q * 256] = z;
        }
        return;
    }

    const int start = i + 257;
    const int s16 = start & ~15;
    const int nv4 = (4096 - s16) >> 2;
    float4* live = (float4*)(p + s16);

    float4 v[4];
    float mx = -FMAXV;
    #pragma unroll
    for (int q = 0; q < 4; q++) {
        int i4 = tid + q * 256;
        if (i4 < nv4) {
            float4 tv = live[i4];
            int j0 = s16 + i4 * 4;
            if (j0 < start) {
                if (j0 + 0 < start) tv.x = -FMAXV;
                if (j0 + 1 < start) tv.y = -FMAXV;
                if (j0 + 2 < start) tv.z = -FMAXV;
                if (j0 + 3 < start) tv.w = -FMAXV;
            }
            v[q] = tv;
            mx = fmaxf(mx, fmaxf(fmaxf(tv.x, tv.y), fmaxf(tv.z, tv.w)));
        }
    }
    #pragma unroll
    for (int o = 16; o > 0; o >>= 1) mx = fmaxf(mx, __shfl_xor_sync(0xffffffffu, mx, o));
    __shared__ float red[8];
    if ((tid & 31) == 0) red[tid >> 5] = mx;
    __syncthreads();
    mx = red[0];
    #pragma unroll
    for (int ww = 1; ww < 8; ww++) mx = fmaxf(mx, red[ww]);
    __syncthreads();

    float s = 0.f;
    #pragma unroll
    for (int q = 0; q < 4; q++) {
        if (tid + q * 256 < nv4) {
            v[q].x = expf(v[q].x - mx); s += v[q].x;
            v[q].y = expf(v[q].y - mx); s += v[q].y;
            v[q].z = expf(v[q].z - mx); s += v[q].z;
            v[q].w = expf(v[q].w - mx); s += v[q].w;
        }
    }
    #pragma unroll
    for (int o = 16; o > 0; o >>= 1) s += __shfl_xor_sync(0xffffffffu, s, o);
    if ((tid & 31) == 0) red[tid >> 5] = s;
    __syncthreads();
    s = red[0];
    #pragma unroll
    for (int ww = 1; ww < 8; ww++) s += red[ww];

    float inv = 1.0f / s;
    uint2* bhl = (uint2*)(bhp + s16);
    uint2* bll = (uint2*)(blp + s16);
    #pragma unroll
    for (int q = 0; q < 4; q++) {
        int i4 = tid + q * 256;
        if (i4 < nv4) {
            v[q].x *= inv; v[q].y *= inv; v[q].z *= inv; v[q].w *= inv;
            live[i4] = v[q];
            uint32_t l0, l1;
            uint32_t h0 = split2_u32(v[q].x, v[q].y, &l0);
            uint32_t h1 = split2_u32(v[q].z, v[q].w, &l1);
            bhl[i4] = make_uint2(h0, h1);
            bll[i4] = make_uint2(l0, l1);
        }
    }
    // zero heads
    float4 z4 = make_float4(0.f, 0.f, 0.f, 0.f);
    int nz4 = s16 >> 2;
    for (int i4 = tid; i4 < nz4; i4 += 256) ((float4*)p)[i4] = z4;
    uint2 z2 = make_uint2(0, 0);
    for (int i2 = tid; i2 < nz4; i2 += 256) {
        ((uint2*)bhp)[i2] = z2;
        ((uint2*)blp)[i2] = z2;
    }
}

// ============================================================
// Host
// ============================================================
extern "C" void kernel_launch(void* const* d_in, const int* in_sizes, int n_in,
                              void* d_out, int out_size)
{
    const float* x    = (const float*)d_in[0];
    const float* WK   = (const float*)d_in[1];
    const float* WQ   = (const float*)d_in[2];
    const float* WV   = (const float*)d_in[3];
    const float* Wout = (const float*)d_in[4];

    const int m = 1024;
    const int n = in_sizes[0] / m;   // 4096

    float* y_out = (float*)d_out;                 // [n, m]
    float* att   = y_out + (size_t)n * m;         // [n, n]

    __nv_bfloat16 *pxS, *pWcat, *pWV, *pWo, *pKQU, *pattB;
    float *pu, *ppart;
    cudaGetSymbolAddress((void**)&pxS,   g_xS);
    cudaGetSymbolAddress((void**)&pWcat, g_Wcat);
    cudaGetSymbolAddress((void**)&pWV,   g_WVs);
    cudaGetSymbolAddress((void**)&pWo,   g_Wos);
    cudaGetSymbolAddress((void**)&pKQU,  g_KQU);
    cudaGetSymbolAddress((void**)&pattB, g_attB);
    cudaGetSymbolAddress((void**)&ppart, g_part);
    cudaGetSymbolAddress((void**)&pu,    g_u);

    // dynamic smem per instantiation
    const int SM01 = 3 * (2 * (128 * 40) + 2 * (32 * 136)) * 2;  // BK32/NS3: 113664
    const int SM00 = 4 * (4 * (128 * 24)) * 2;                   // BK16/NS4: 98304
    const int SM11 = 3 * (4 * (32 * 136)) * 2;                   // BK32/NS3: 104448

    cudaFuncSetAttribute(gemm_bf16<0, 1, 0, 0, 32, 3>, cudaFuncAttributeMaxDynamicSharedMemorySize, SM01);
    cudaFuncSetAttribute(gemm_bf16<0, 1, 3, 0, 32, 3>, cudaFuncAttributeMaxDynamicSharedMemorySize, SM01);
    cudaFuncSetAttribute(gemm_bf16<0, 0, 1, 1, 16, 4>, cudaFuncAttributeMaxDynamicSharedMemorySize, SM00);
    cudaFuncSetAttribute(gemm_bf16<1, 1, 1, 2, 32, 3>, cudaFuncAttributeMaxDynamicSharedMemorySize, SM11);

    const long long PX   = 4096LL * 1024;   // xS plane
    const long long PW   = 1024LL * 1024;   // dense weight plane
    const long long PCAT = 1024LL * 3072;   // Wcat plane
    const long long PKQ  = 4096LL * 3072;   // KQU plane
    const long long PA   = 4096LL * 4096;   // attB plane

    // Elementwise splits only — NO transposes.
    split_kernel<<<2048, 256>>>(x, pxS, (size_t)n * m);
    splitW_kernel<<<dim3(512, 4), 256>>>(WK, WQ, WV, Wout, pWcat, pWV, pWo);

    // W2 = WV@Wout -> bf16 split into Wcat cols [2048,3072)
    gemm_bf16<0, 1, 0, 0, 32, 3><<<dim3(8, 8), 256, SM01>>>(
        pWV, pWo, pWcat + 2048, 1024, 1024, 3072, PW, PW, PCAT, 32, 1.0f, nullptr);

    // Fused K|Q|U = x @ Wcat  (Q block scaled by 0.06 in epilogue) -> KQU split
    gemm_bf16<0, 1, 3, 0, 32, 3><<<dim3(24, 32), 256, SM01>>>(
        pxS, pWcat, pKQU, 1024, 3072, 3072, PX, PCAT, PKQ, 32, 0.06f, nullptr);

    // logits = Q@K^T (A = KQU+1024, B = KQU+0, both ld 3072) -> fp32 att
    gemm_bf16<0, 0, 1, 1, 16, 4><<<dim3(32, 32), 256, SM00>>>(
        pKQU + 1024, pKQU, att, 3072, 3072, 4096, PKQ, PKQ, 0, 64, 1.0f, nullptr);

    // softmax + fused bf16 split (row-major planes)
    softmax_split<<<n, 256>>>(att, pattB, PA);

    // rank-1 uniform-row vector from U planes (inside KQU)
    rank1_kernel<<<8, 1024>>>(pKQU + 2048, pu, 3072, PKQ);

    // y_partial = att^T @ U  (split-K x2, longest-first; z=0 -> y_out, z=1 -> part)
    gemm_bf16<1, 1, 1, 2, 32, 3><<<dim3(8, 32, 2), 256, SM11>>>(
        pattB, pKQU + 2048, y_out, 4096, 3072, 1024, PA, PKQ, 0, 128, 1.0f, ppart);

    // y = y + part + u
    combine_kernel<<<2048, 256>>>(y_out, ppart, pu);
}

// round 17
// speedup vs baseline: 1.5220x; 1.0892x over previous
#include <cuda_runtime.h>
#include <cuda_bf16.h>
#include <stdint.h>

#define FMAXV 3.4028235e38f

// ============================================================
// Device scratch (allocation-free). All split buffers: 2 bf16 planes
// (hi, residual), native layouts, no transposes.
// Reassociation: y = att^T @ (x @ (WV@Wout)) + u.
// Wcat packs [WK | WQ | W2] column-wise: [1024][3072] trans layout.
// KQU packs [K | Q | U] column-wise: [4096][3072].
// ============================================================
__device__ __nv_bfloat16 g_xS  [2ull*4096*1024];   // [n][m]
__device__ __nv_bfloat16 g_Wcat[2ull*1024*3072];   // [k][3n]: WK|WQ|W2
__device__ __nv_bfloat16 g_WVs [2ull*1024*1024];   // [m][d] (W2 gemm A)
__device__ __nv_bfloat16 g_Wos [2ull*1024*1024];   // [d][m] (W2 gemm B, trans)
__device__ __nv_bfloat16 g_KQU [2ull*4096*3072];   // [j][3k]: K|Q|U
__device__ __nv_bfloat16 g_attB[2ull*4096*4096];   // [r][a] (from softmax)
__device__ float         g_part[4096ull*1024];     // attV split-K partial
__device__ float         g_u   [1024];

// ============================================================
// Helpers (base sm_103-safe: mma.sync bf16, cp.async, ldmatrix)
// ============================================================
__device__ __forceinline__ uint32_t smem_u32(const void* p) {
    uint32_t a;
    asm("{ .reg .u64 t; cvta.to.shared.u64 t, %1; cvt.u32.u64 %0, t; }" : "=r"(a) : "l"(p));
    return a;
}
__device__ __forceinline__ void cp16(void* s, const void* g) {
    uint32_t a = smem_u32(s);
    asm volatile("cp.async.cg.shared.global [%0], [%1], 16;" :: "r"(a), "l"(g));
}
#define CP_COMMIT()  asm volatile("cp.async.commit_group;" ::: "memory")
#define CP_WAIT(N)   asm volatile("cp.async.wait_group %0;" :: "n"(N) : "memory")

__device__ __forceinline__ void ldsm4(uint32_t* r, uint32_t a) {
    asm volatile("ldmatrix.sync.aligned.m8n8.x4.shared.b16 {%0,%1,%2,%3}, [%4];"
        : "=r"(r[0]), "=r"(r[1]), "=r"(r[2]), "=r"(r[3]) : "r"(a));
}
__device__ __forceinline__ void ldsm4t(uint32_t* r, uint32_t a) {
    asm volatile("ldmatrix.sync.aligned.m8n8.x4.trans.shared.b16 {%0,%1,%2,%3}, [%4];"
        : "=r"(r[0]), "=r"(r[1]), "=r"(r[2]), "=r"(r[3]) : "r"(a));
}
__device__ __forceinline__ void ldsm2(uint32_t* r, uint32_t a) {
    asm volatile("ldmatrix.sync.aligned.m8n8.x2.shared.b16 {%0,%1}, [%2];"
        : "=r"(r[0]), "=r"(r[1]) : "r"(a));
}
__device__ __forceinline__ void ldsm2t(uint32_t* r, uint32_t a) {
    asm volatile("ldmatrix.sync.aligned.m8n8.x2.trans.shared.b16 {%0,%1}, [%2];"
        : "=r"(r[0]), "=r"(r[1]) : "r"(a));
}
__device__ __forceinline__ void mma16(float* c, const uint32_t* a, const uint32_t* b) {
    asm volatile(
        "mma.sync.aligned.m16n8k16.row.col.f32.bf16.bf16.f32 "
        "{%0,%1,%2,%3}, {%4,%5,%6,%7}, {%8,%9}, {%0,%1,%2,%3};"
        : "+f"(c[0]), "+f"(c[1]), "+f"(c[2]), "+f"(c[3])
        : "r"(a[0]), "r"(a[1]), "r"(a[2]), "r"(a[3]), "r"(b[0]), "r"(b[1]));
}
__device__ __forceinline__ uint32_t split2_u32(float v0, float v1, uint32_t* lo) {
    __nv_bfloat16 h0 = __float2bfloat16_rn(v0);
    __nv_bfloat16 h1 = __float2bfloat16_rn(v1);
    __nv_bfloat16 l0 = __float2bfloat16_rn(v0 - __bfloat162float(h0));
    __nv_bfloat16 l1 = __float2bfloat16_rn(v1 - __bfloat162float(h1));
    *lo = (uint32_t)__bfloat16_as_ushort(l0) | ((uint32_t)__bfloat16_as_ushort(l1) << 16);
    return (uint32_t)__bfloat16_as_ushort(h0) | ((uint32_t)__bfloat16_as_ushort(h1) << 16);
}

// ============================================================
// GEMM (R6 core schedule): D[m,n] = sum_k A[m,k]*B[n,k].
// A,B = 2-plane bf16 split; 3 products/K16 (Ah*Bh + Ah*Bm + Am*Bh).
// Tile 128x128, 256 thr (8 warps, 64x32), NS-stage cp.async,
// one barrier per BK-chunk, issue() at END of loop body.
// EPI: 0 = bf16 split out; 1 = fp32 out;
//      3 = bf16 split out, alpha applied ONLY to JB-block 1 (fused Q scale)
// SKIP: 1 = fully-masked logits tile -> return, no writes
//       2 = attV: IB reversed (longest first), K-chunks j < IB-129,
//           blockIdx.z halves the chunk range; z=1 writes Cv2.
// ============================================================
template <int TRA, int TRB, int EPI, int SKIP, int BK, int NS>
__global__ void __launch_bounds__(256, 2)
gemm_bf16(const __nv_bfloat16* __restrict__ A, const __nv_bfloat16* __restrict__ B,
          void* __restrict__ Cv, int lda, int ldb, int ldc,
          long long planeA, long long planeB, long long planeC,
          int nch, float alpha, void* __restrict__ Cv2)
{
    constexpr int AROW = TRA ? 136 : (BK + 8);    // padded row strides (halves)
    constexpr int BROW = TRB ? 136 : (BK + 8);
    constexpr int APL  = TRA ? BK * 136 : 128 * (BK + 8);
    constexpr int BPL  = TRB ? BK * 136 : 128 * (BK + 8);
    constexpr int STG  = 2 * APL + 2 * BPL;       // Ah, Am, Bh, Bm (halves)
    constexpr int KSN  = BK / 16;                 // k16 sub-chunks per chunk

    const int tid = threadIdx.x;
    const int IBb = (SKIP == 2) ? (31 - blockIdx.y) : blockIdx.y;
    const int IB = IBb * 128;
    const int JB = blockIdx.x * 128;

    if (SKIP == 1 && (JB + 127 - IB) <= 256) return;

    extern __shared__ __nv_bfloat16 smh[];

    int t0 = 0, t1 = nch;
    if (SKIP == 2) {
        int n1 = IB - 129; if (n1 < 0) n1 = 0;
        int T = (n1 + BK - 1) / BK; if (T > nch) T = nch;
        int Th = (T + 1) >> 1;
        if (blockIdx.z == 0) { t1 = Th; }
        else                 { t0 = Th; t1 = T; Cv = Cv2; }
    }

    const int lane = tid & 31, w = tid >> 5;
    const int RW = (w >> 2) * 64, CW = (w & 3) * 32;

    // ldmatrix per-lane offsets (halves within plane)
    const int lq = lane >> 3, li = lane & 7, q2 = lq & 1;
    int aoff, boff;
    if (TRA) aoff = ((lq >> 1) * 8 + li) * AROW + RW + (lq & 1) * 8;
    else     aoff = (RW + (lq & 1) * 8 + li) * AROW + (lq >> 1) * 8;
    if (TRB) boff = (q2 * 8 + li) * BROW + CW;
    else     boff = (CW + li) * BROW + q2 * 8;
    constexpr int AMT = TRA ? 16 : 16 * AROW;     // per-mt advance
    constexpr int BNT = TRB ? 8 : 8 * BROW;       // per-nt advance
    constexpr int AKS = TRA ? 16 * 136 : 16;      // per-k16 advance
    constexpr int BKS = TRB ? 16 * 136 : 16;
    const uint32_t sb0 = smem_u32(smh);

    auto issue = [&](int t) {
        int k0 = t * BK;
        __nv_bfloat16* sb = smh + (t % NS) * STG;
        constexpr int APPL = TRA ? BK * 16 : 128 * (BK / 8);  // cp16 per A plane
        constexpr int AIT  = (2 * APPL) / 256;
        #pragma unroll
        for (int it = 0; it < AIT; it++) {
            int idx = tid + it * 256;
            int pl = idx / APPL, r = idx % APPL;
            __nv_bfloat16* dst; const __nv_bfloat16* src;
            if (TRA) { int row = r >> 4, ch = r & 15;
                dst = sb + pl * APL + row * AROW + ch * 8;
                src = A + (size_t)pl * planeA + (size_t)(k0 + row) * lda + IB + ch * 8;
            } else { int row = r / (BK / 8), ch = r % (BK / 8);
                dst = sb + pl * APL + row * AROW + ch * 8;
                src = A + (size_t)pl * planeA + (size_t)(IB + row) * lda + k0 + ch * 8;
            }
            cp16(dst, src);
        }
        constexpr int BPPL = TRB ? BK * 16 : 128 * (BK / 8);
        constexpr int BIT  = (2 * BPPL) / 256;
        #pragma unroll
        for (int it = 0; it < BIT; it++) {
            int idx = tid + it * 256;
            int pl = idx / BPPL, r = idx % BPPL;
            __nv_bfloat16* dst; const __nv_bfloat16* src;
            if (TRB) { int row = r >> 4, ch = r & 15;
                dst = sb + 2 * APL + pl * BPL + row * BROW + ch * 8;
                src = B + (size_t)pl * planeB + (size_t)(k0 + row) * ldb + JB + ch * 8;
            } else { int row = r / (BK / 8), ch = r % (BK / 8);
                dst = sb + 2 * APL + pl * BPL + row * BROW + ch * 8;
                src = B + (size_t)pl * planeB + (size_t)(JB + row) * ldb + k0 + ch * 8;
            }
            cp16(dst, src);
        }
        CP_COMMIT();
    };

    float acc[64];
    #pragma unroll
    for (int i = 0; i < 64; i++) acc[i] = 0.f;

    #pragma unroll
    for (int p = 0; p < NS - 1; p++)
        if (t0 + p < t1) issue(t0 + p);

    for (int t = t0; t < t1; t++) {
        if (NS == 4) {
            if (t + 2 < t1) { CP_WAIT(2); } else if (t + 1 < t1) { CP_WAIT(1); } else { CP_WAIT(0); }
        } else {
            if (t + 1 < t1) { CP_WAIT(1); } else { CP_WAIT(0); }
        }
        __syncthreads();

        uint32_t sbb = sb0 + (uint32_t)((t % NS) * STG) * 2;

        #pragma unroll
        for (int ks = 0; ks < KSN; ks++) {
            uint32_t aH = sbb + (uint32_t)(aoff + ks * AKS) * 2;
            uint32_t aM = aH + APL * 2;
            uint32_t bHa = sbb + (uint32_t)(2 * APL + boff + ks * BKS) * 2;
            uint32_t bMa = bHa + BPL * 2;

            uint32_t af[16], am[16], bh[8], bm[8];
            #pragma unroll
            for (int mt = 0; mt < 4; mt++) {
                if (TRA) ldsm4t(af + mt * 4, aH + mt * AMT * 2);
                else     ldsm4 (af + mt * 4, aH + mt * AMT * 2);
            }
            #pragma unroll
            for (int nt = 0; nt < 4; nt++) {
                if (TRB) ldsm2t(bh + nt * 2, bHa + nt * BNT * 2);
                else     ldsm2 (bh + nt * 2, bHa + nt * BNT * 2);
            }
            #pragma unroll
            for (int mt = 0; mt < 4; mt++)
                #pragma unroll
                for (int nt = 0; nt < 4; nt++)
                    mma16(&acc[(mt * 4 + nt) * 4], af + mt * 4, bh + nt * 2);
            #pragma unroll
            for (int nt = 0; nt < 4; nt++) {
                if (TRB) ldsm2t(bm + nt * 2, bMa + nt * BNT * 2);
                else     ldsm2 (bm + nt * 2, bMa + nt * BNT * 2);
            }
            #pragma unroll
            for (int mt = 0; mt < 4; mt++)
                #pragma unroll
                for (int nt = 0; nt < 4; nt++)
                    mma16(&acc[(mt * 4 + nt) * 4], af + mt * 4, bm + nt * 2);
            #pragma unroll
            for (int mt = 0; mt < 4; mt++) {
                if (TRA) ldsm4t(am + mt * 4, aM + mt * AMT * 2);
                else     ldsm4 (am + mt * 4, aM + mt * AMT * 2);
            }
            #pragma unroll
            for (int mt = 0; mt < 4; mt++)
                #pragma unroll
                for (int nt = 0; nt < 4; nt++)
                    mma16(&acc[(mt * 4 + nt) * 4], am + mt * 4, bh + nt * 2);
        }

        if (t + NS - 1 < t1) issue(t + NS - 1);   // writes stage (t-1)%NS, freed by top barrier
    }

    // ---------------- epilogue ----------------
    const float al = (EPI == 3) ? (((JB >> 10) == 1) ? alpha : 1.0f) : alpha;
    const int eg = lane >> 2, etg = lane & 3;
    #pragma unroll
    for (int mt = 0; mt < 4; mt++) {
        #pragma unroll
        for (int nt = 0; nt < 4; nt++) {
            const float* cc = &acc[(mt * 4 + nt) * 4];
            int r0 = IB + RW + mt * 16 + eg;
            int c0 = JB + CW + nt * 8 + 2 * etg;
            #pragma unroll
            for (int half = 0; half < 2; half++) {
                int r = r0 + half * 8;
                float v0 = cc[half * 2 + 0] * al;
                float v1 = cc[half * 2 + 1] * al;
                if (EPI == 1) {
                    *(float2*)((float*)Cv + (size_t)r * ldc + c0) = make_float2(v0, v1);
                } else {
                    __nv_bfloat16* dst = (__nv_bfloat16*)Cv + (size_t)r * ldc + c0;
                    uint32_t lo;
                    uint32_t hi = split2_u32(v0, v1, &lo);
                    *(uint32_t*)dst            = hi;
                    *(uint32_t*)(dst + planeC) = lo;
                }
            }
        }
    }
}

// ============================================================
// Elementwise split to 2 bf16 planes (float4 vectorized)
// ============================================================
__global__ void __launch_bounds__(256)
split_kernel(const float* __restrict__ in, __nv_bfloat16* __restrict__ out, size_t S)
{
    size_t S4 = S >> 2;
    uint32_t* oh = (uint32_t*)out;
    uint32_t* ol = (uint32_t*)(out + S);
    for (size_t i4 = (size_t)blockIdx.x * blockDim.x + threadIdx.x; i4 < S4;
         i4 += (size_t)gridDim.x * blockDim.x) {
        float4 v = ((const float4*)in)[i4];
        uint32_t l0, l1;
        uint32_t h0 = split2_u32(v.x, v.y, &l0);
        uint32_t h1 = split2_u32(v.z, v.w, &l1);
        oh[i4 * 2] = h0; oh[i4 * 2 + 1] = h1;
        ol[i4 * 2] = l0; ol[i4 * 2 + 1] = l1;
    }
}

// Fused weight split: y=0 -> WK into Wcat cols [0,1024); y=1 -> WQ into
// Wcat cols [1024,2048); y=2 -> WV dense; y=3 -> Wout dense.
__global__ void __launch_bounds__(256)
splitW_kernel(const float* __restrict__ w0, const float* __restrict__ w1,
              const float* __restrict__ w2, const float* __restrict__ w3,
              __nv_bfloat16* __restrict__ wcat,
              __nv_bfloat16* __restrict__ ov, __nv_bfloat16* __restrict__ oo)
{
    const size_t S = 1024ull * 1024;
    const size_t PCAT = 1024ull * 3072;
    size_t S4 = S >> 2;
    const int which = blockIdx.y;
    const float* in = (which == 0) ? w0 : (which == 1) ? w1 : (which == 2) ? w2 : w3;

    for (size_t i4 = (size_t)blockIdx.x * blockDim.x + threadIdx.x; i4 < S4;
         i4 += (size_t)gridDim.x * blockDim.x) {
        float4 v = ((const float4*)in)[i4];
        uint32_t l0, l1;
        uint32_t h0 = split2_u32(v.x, v.y, &l0);
        uint32_t h1 = split2_u32(v.z, v.w, &l1);
        if (which < 2) {
            size_t e = i4 * 4;
            size_t row = e >> 10, col = e & 1023;
            size_t o = row * 3072 + which * 1024 + col;   // halves, 4-aligned
            uint2* dh = (uint2*)(wcat + o);
            uint2* dl = (uint2*)(wcat + PCAT + o);
            *dh = make_uint2(h0, h1);
            *dl = make_uint2(l0, l1);
        } else {
            __nv_bfloat16* out = (which == 2) ? ov : oo;
            uint32_t* oh = (uint32_t*)out;
            uint32_t* ol = (uint32_t*)(out + S);
            oh[i4 * 2] = h0; oh[i4 * 2 + 1] = h1;
            ol[i4 * 2] = l0; ol[i4 * 2 + 1] = l1;
        }
    }
}

// ============================================================
// rank-1 uniform-row correction from U planes (inside KQU):
// u[k] = (1/4096) * sum_{j>=3839} (Uh+Ul)[j][k]
// ============================================================
__global__ void __launch_bounds__(1024)
rank1_kernel(const __nv_bfloat16* __restrict__ Up, float* __restrict__ u,
             int ld, long long plane)
{
    __shared__ float part[8][128];
    const int kl = threadIdx.x & 127;
    const int js = threadIdx.x >> 7;          // 0..7
    const int k = blockIdx.x * 128 + kl;
    float s = 0.f;
    for (int j = 3839 + js; j < 4096; j += 8) {
        size_t o = (size_t)j * ld + k;
        s += __bfloat162float(Up[o]) + __bfloat162float(Up[plane + o]);
    }
    part[js][kl] = s;
    __syncthreads();
    if (threadIdx.x < 128) {
        float t = 0.f;
        #pragma unroll
        for (int q = 0; q < 8; q++) t += part[q][threadIdx.x];
        u[k] = t * (1.0f / 4096.0f);
    }
}

// ============================================================
// Combine: y[i][k] = part0(y in-place) + part1 + u[k]
// ============================================================
__global__ void __launch_bounds__(256)
combine_kernel(float* __restrict__ y, const float* __restrict__ part,
               const float* __restrict__ u)
{
    const size_t S4 = (4096ull * 1024) >> 2;
    for (size_t i4 = (size_t)blockIdx.x * blockDim.x + threadIdx.x; i4 < S4;
         i4 += (size_t)gridDim.x * blockDim.x) {
        float4 a = ((float4*)y)[i4];
        float4 b = ((const float4*)part)[i4];
        float4 uu = ((const float4*)u)[i4 & 255];   // k = (i4*4) % 1024
        a.x += b.x + uu.x; a.y += b.y + uu.y;
        a.z += b.z + uu.z; a.w += b.w + uu.w;
        ((float4*)y)[i4] = a;
    }
}

// ============================================================
// Structured softmax + fused bf16 split, one block per row.
// Row i < 3839: fp32 row fully correct (zero head + live); bf16 planes
// zero only a 160-col band before the live start — attV provably reads
// no earlier masked cols (i - j >= 99 for all CTA/chunk bounds).
// Rows i >= 3839: fp32 = 1/4096 exactly, bf16 planes = 0.
// ============================================================
__global__ void __launch_bounds__(256)
softmax_split(float* __restrict__ att, __nv_bfloat16* __restrict__ ab, long long PA)
{
    const int i = blockIdx.x;
    const int tid = threadIdx.x;
    float* p = att + (size_t)i * 4096;
    __nv_bfloat16* bhp = ab + (size_t)i * 4096;
    __nv_bfloat16* blp = bhp + PA;

    if (i >= 3839) {
        const float c = 1.0f / 4096.0f;
        float4 cv = make_float4(c, c, c, c);
        #pragma unroll
        for (int q = 0; q < 4; q++) ((float4*)p)[tid + q * 256] = cv;
        uint4 z = make_uint4(0, 0, 0, 0);
        #pragma unroll
        for (int q = 0; q < 2; q++) {
            ((uint4*)bhp)[tid + q * 256] = z;
            ((uint4*)blp)[tid + q * 256] = z;
        }
        return;
    }

    const int start = i + 257;
    const int s16 = start & ~15;
    const int nv4 = (4096 - s16) >> 2;
    float4* live = (float4*)(p + s16);

    float4 v[4];
    float mx = -FMAXV;
    #pragma unroll
    for (int q = 0; q < 4; q++) {
        int i4 = tid + q * 256;
        if (i4 < nv4) {
            float4 tv = live[i4];
            int j0 = s16 + i4 * 4;
            if (j0 < start) {
                if (j0 + 0 < start) tv.x = -FMAXV;
                if (j0 + 1 < start) tv.y = -FMAXV;
                if (j0 + 2 < start) tv.z = -FMAXV;
                if (j0 + 3 < start) tv.w = -FMAXV;
            }
            v[q] = tv;
            mx = fmaxf(mx, fmaxf(fmaxf(tv.x, tv.y), fmaxf(tv.z, tv.w)));
        }
    }
    #pragma unroll
    for (int o = 16; o > 0; o >>= 1) mx = fmaxf(mx, __shfl_xor_sync(0xffffffffu, mx, o));
    __shared__ float red[8];
    if ((tid & 31) == 0) red[tid >> 5] = mx;
    __syncthreads();
    mx = red[0];
    #pragma unroll
    for (int ww = 1; ww < 8; ww++) mx = fmaxf(mx, red[ww]);
    __syncthreads();

    float s = 0.f;
    #pragma unroll
    for (int q = 0; q < 4; q++) {
        if (tid + q * 256 < nv4) {
            v[q].x = expf(v[q].x - mx); s += v[q].x;
            v[q].y = expf(v[q].y - mx); s += v[q].y;
            v[q].z = expf(v[q].z - mx); s += v[q].z;
            v[q].w = expf(v[q].w - mx); s += v[q].w;
        }
    }
    #pragma unroll
    for (int o = 16; o > 0; o >>= 1) s += __shfl_xor_sync(0xffffffffu, s, o);
    if ((tid & 31) == 0) red[tid >> 5] = s;
    __syncthreads();
    s = red[0];
    #pragma unroll
    for (int ww = 1; ww < 8; ww++) s += red[ww];

    float inv = 1.0f / s;
    uint2* bhl = (uint2*)(bhp + s16);
    uint2* bll = (uint2*)(blp + s16);
    #pragma unroll
    for (int q = 0; q < 4; q++) {
        int i4 = tid + q * 256;
        if (i4 < nv4) {
            v[q].x *= inv; v[q].y *= inv; v[q].z *= inv; v[q].w *= inv;
            live[i4] = v[q];
            uint32_t l0, l1;
            uint32_t h0 = split2_u32(v[q].x, v[q].y, &l0);
            uint32_t h1 = split2_u32(v[q].z, v[q].w, &l1);
            bhl[i4] = make_uint2(h0, h1);
            bll[i4] = make_uint2(l0, l1);
        }
    }
    // zero fp32 head fully (checked output)
    float4 z4 = make_float4(0.f, 0.f, 0.f, 0.f);
    int nz4 = s16 >> 2;
    for (int i4 = tid; i4 < nz4; i4 += 256) ((float4*)p)[i4] = z4;
    // zero bf16 planes only in the 160-col band before s16 (all attV reads)
    int zlo = s16 - 160; if (zlo < 0) zlo = 0;
    int zb0 = zlo >> 2, zb1 = s16 >> 2;
    uint2 z2 = make_uint2(0, 0);
    for (int i2 = zb0 + tid; i2 < zb1; i2 += 256) {
        ((uint2*)bhp)[i2] = z2;
        ((uint2*)blp)[i2] = z2;
    }
}

// ============================================================
// Host — stream fork/join (graph-capturable) to overlap W2, splits, rank1
// ============================================================
extern "C" void kernel_launch(void* const* d_in, const int* in_sizes, int n_in,
                              void* d_out, int out_size)
{
    const float* x    = (const float*)d_in[0];
    const float* WK   = (const float*)d_in[1];
    const float* WQ   = (const float*)d_in[2];
    const float* WV   = (const float*)d_in[3];
    const float* Wout = (const float*)d_in[4];

    const int m = 1024;
    const int n = in_sizes[0] / m;   // 4096

    float* y_out = (float*)d_out;                 // [n, m]
    float* att   = y_out + (size_t)n * m;         // [n, n]

    __nv_bfloat16 *pxS, *pWcat, *pWV, *pWo, *pKQU, *pattB;
    float *pu, *ppart;
    cudaGetSymbolAddress((void**)&pxS,   g_xS);
    cudaGetSymbolAddress((void**)&pWcat, g_Wcat);
    cudaGetSymbolAddress((void**)&pWV,   g_WVs);
    cudaGetSymbolAddress((void**)&pWo,   g_Wos);
    cudaGetSymbolAddress((void**)&pKQU,  g_KQU);
    cudaGetSymbolAddress((void**)&pattB, g_attB);
    cudaGetSymbolAddress((void**)&ppart, g_part);
    cudaGetSymbolAddress((void**)&pu,    g_u);

    // dynamic smem per instantiation
    const int SM01 = 3 * (2 * (128 * 40) + 2 * (32 * 136)) * 2;  // BK32/NS3: 113664
    const int SM00 = 4 * (4 * (128 * 24)) * 2;                   // BK16/NS4: 98304
    const int SM11 = 3 * (4 * (32 * 136)) * 2;                   // BK32/NS3: 104448

    cudaFuncSetAttribute(gemm_bf16<0, 1, 0, 0, 32, 3>, cudaFuncAttributeMaxDynamicSharedMemorySize, SM01);
    cudaFuncSetAttribute(gemm_bf16<0, 1, 3, 0, 32, 3>, cudaFuncAttributeMaxDynamicSharedMemorySize, SM01);
    cudaFuncSetAttribute(gemm_bf16<0, 0, 1, 1, 16, 4>, cudaFuncAttributeMaxDynamicSharedMemorySize, SM00);
    cudaFuncSetAttribute(gemm_bf16<1, 1, 1, 2, 32, 3>, cudaFuncAttributeMaxDynamicSharedMemorySize, SM11);

    const long long PX   = 4096LL * 1024;   // xS plane
    const long long PW   = 1024LL * 1024;   // dense weight plane
    const long long PCAT = 1024LL * 3072;   // Wcat plane
    const long long PKQ  = 4096LL * 3072;   // KQU plane
    const long long PA   = 4096LL * 4096;   // attB plane

    cudaStream_t s2;
    cudaStreamCreateWithFlags(&s2, cudaStreamNonBlocking);
    cudaEvent_t evFork, evW, evW2, evU, evR;
    cudaEventCreateWithFlags(&evFork, cudaEventDisableTiming);
    cudaEventCreateWithFlags(&evW,    cudaEventDisableTiming);
    cudaEventCreateWithFlags(&evW2,   cudaEventDisableTiming);
    cudaEventCreateWithFlags(&evU,    cudaEventDisableTiming);
    cudaEventCreateWithFlags(&evR,    cudaEventDisableTiming);

    // Fork side stream from main stream
    cudaEventRecord(evFork, 0);
    cudaStreamWaitEvent(s2, evFork, 0);

    // s2: weight splits -> W2 GEMM (overlaps split_x and KQ on main stream)
    splitW_kernel<<<dim3(512, 4), 256, 0, s2>>>(WK, WQ, WV, Wout, pWcat, pWV, pWo);
    cudaEventRecord(evW, s2);
    gemm_bf16<0, 1, 0, 0, 32, 3><<<dim3(8, 8), 256, SM01, s2>>>(
        pWV, pWo, pWcat + 2048, 1024, 1024, 3072, PW, PW, PCAT, 32, 1.0f, nullptr);
    cudaEventRecord(evW2, s2);

    // main: split x, then K|Q (needs Wcat cols 0..2047 from splitW)
    split_kernel<<<2048, 256>>>(x, pxS, (size_t)n * m);
    cudaStreamWaitEvent(0, evW, 0);
    gemm_bf16<0, 1, 3, 0, 32, 3><<<dim3(16, 32), 256, SM01>>>(
        pxS, pWcat, pKQU, 1024, 3072, 3072, PX, PCAT, PKQ, 32, 0.06f, nullptr);

    // main: U = x @ W2 (needs evW2)
    cudaStreamWaitEvent(0, evW2, 0);
    gemm_bf16<0, 1, 0, 0, 32, 3><<<dim3(8, 32), 256, SM01>>>(
        pxS, pWcat + 2048, pKQU + 2048, 1024, 3072, 3072, PX, PCAT, PKQ, 32, 1.0f, nullptr);
    cudaEventRecord(evU, 0);

    // s2: rank-1 vector from U planes (overlaps logits/softmax)
    cudaStreamWaitEvent(s2, evU, 0);
    rank1_kernel<<<8, 1024, 0, s2>>>(pKQU + 2048, pu, 3072, PKQ);
    cudaEventRecord(evR, s2);

    // main: logits = Q@K^T -> fp32 att
    gemm_bf16<0, 0, 1, 1, 16, 4><<<dim3(32, 32), 256, SM00>>>(
        pKQU + 1024, pKQU, att, 3072, 3072, 4096, PKQ, PKQ, 0, 64, 1.0f, nullptr);

    // main: softmax + fused bf16 split (banded zeroing)
    softmax_split<<<n, 256>>>(att, pattB, PA);

    // main: y_partial = att^T @ U (split-K x2, longest-first)
    gemm_bf16<1, 1, 1, 2, 32, 3><<<dim3(8, 32, 2), 256, SM11>>>(
        pattB, pKQU + 2048, y_out, 4096, 3072, 1024, PA, PKQ, 0, 128, 1.0f, ppart);

    // join rank-1, then combine
    cudaStreamWaitEvent(0, evR, 0);
    combine_kernel<<<2048, 256>>>(y_out, ppart, pu);

    cudaEventDestroy(evFork);
    cudaEventDestroy(evW);
    cudaEventDestroy(evW2);
    cudaEventDestroy(evU);
    cudaEventDestroy(evR);
    cudaStreamDestroy(s2);
}